// round 3
// baseline (speedup 1.0000x reference)
#include <cuda_runtime.h>
#include <math.h>

#define BSZ 4096
#define DD  64
#define HH  256
#define NN  32
#define BROFF (BSZ * HH)

// ---------------- scratch (device globals; no allocation allowed) ----------
__device__ float g_h1[2 * BSZ * HH];
__device__ float g_p1[2 * BSZ * HH];
__device__ float g_p2[2 * BSZ * HH];
__device__ float g_u2[2 * BSZ * HH];
__device__ float g_bv[2 * BSZ * HH];
__device__ float g_wv[2 * BSZ * HH];
__device__ float g_av[2 * BSZ * HH];
__device__ float g_jl[BSZ * DD];
__device__ float g_W1T[2 * HH * DD];   // [k][r]  (256x64 per branch)
__device__ float g_W2T[2 * HH * HH];   // [j][i]  (256x256 per branch)

// ---------------- activations ----------------------------------------------
__device__ __forceinline__ void act_sp(float z, float& h, float& d1, float& d2) {
    float s = 1.0f / (1.0f + expf(-z));
    h  = fmaxf(z, 0.0f) + log1pf(expf(-fabsf(z)));
    d1 = s;
    d2 = s * (1.0f - s);
}
__device__ __forceinline__ void act_q(float z, float& h, float& d1, float& d2) {
    // phi(z) = z*tanh(0.5 z)
    float t = tanhf(0.5f * z);
    float c = 1.0f - t * t;
    h  = z * t;
    d1 = t + 0.5f * z * c;
    d2 = c * (1.0f - 0.5f * z * t);
}

// ---------------- transpose helper ------------------------------------------
__global__ void k_transpose(const float* __restrict__ W1m, const float* __restrict__ W1q,
                            const float* __restrict__ W2m, const float* __restrict__ W2q) {
    int tid = blockIdx.x * blockDim.x + threadIdx.x;
    if (tid < 16384) {
        int r = tid / 256, k = tid % 256;
        g_W1T[k * 64 + r] = W1m[tid];
    } else if (tid < 32768) {
        int t = tid - 16384; int r = t / 256, k = t % 256;
        g_W1T[16384 + k * 64 + r] = W1q[t];
    } else if (tid < 98304) {
        int t = tid - 32768; int i = t / 256, j = t % 256;
        g_W2T[j * 256 + i] = W2m[t];
    } else if (tid < 163840) {
        int t = tid - 98304; int i = t / 256, j = t % 256;
        g_W2T[65536 + j * 256 + i] = W2q[t];
    }
}

// ---------------- generic 64x64-tile GEMM with fused epilogues --------------
#define EPI_L1_SP 0
#define EPI_L1_Q  1
#define EPI_L2_SP 2
#define EPI_L2_Q  3
#define EPI_V1    4
#define EPI_G_ST  5
#define EPI_G_ADD 6

__global__ __launch_bounds__(256)
void k_gemm(const float* __restrict__ A, const float* __restrict__ Bm,
            int K, int N, int epi,
            const float* __restrict__ bias, const float* __restrict__ w3,
            const float* __restrict__ e1, const float* __restrict__ e2,
            float* __restrict__ o1, float* __restrict__ o2, float* __restrict__ o3) {
    __shared__ float sA[16][65];
    __shared__ float sB[16][64];
    int tid = threadIdx.x;
    int bm = blockIdx.x * 64, bn = blockIdx.y * 64;
    int ty = tid >> 4, tx = tid & 15;
    int ar = tid >> 2, akq = (tid & 3) * 4;
    int bk = tid >> 4, bnq = (tid & 15) * 4;
    float acc[4][4] = {};
    for (int k0 = 0; k0 < K; k0 += 16) {
        float4 av = *(const float4*)(A + (size_t)(bm + ar) * K + k0 + akq);
        sA[akq + 0][ar] = av.x; sA[akq + 1][ar] = av.y;
        sA[akq + 2][ar] = av.z; sA[akq + 3][ar] = av.w;
        *(float4*)(&sB[bk][bnq]) = *(const float4*)(Bm + (size_t)(k0 + bk) * N + bn + bnq);
        __syncthreads();
#pragma unroll
        for (int kk = 0; kk < 16; kk++) {
            float a[4], b[4];
#pragma unroll
            for (int i = 0; i < 4; i++) a[i] = sA[kk][ty * 4 + i];
#pragma unroll
            for (int j = 0; j < 4; j++) b[j] = sB[kk][tx * 4 + j];
#pragma unroll
            for (int i = 0; i < 4; i++)
#pragma unroll
                for (int j = 0; j < 4; j++) acc[i][j] += a[i] * b[j];
        }
        __syncthreads();
    }
#pragma unroll
    for (int i = 0; i < 4; i++) {
        int s = bm + ty * 4 + i;
#pragma unroll
        for (int j = 0; j < 4; j++) {
            int c = bn + tx * 4 + j;
            float v = acc[i][j];
            size_t idx = (size_t)s * N + c;
            if (epi == EPI_L1_SP) {
                float h, d1, d2; act_sp(v + bias[c], h, d1, d2);
                o1[idx] = h; o2[idx] = d1; o3[idx] = d2;
            } else if (epi == EPI_L1_Q) {
                float h, d1, d2; act_q(v + bias[c], h, d1, d2);
                o1[idx] = h; o2[idx] = d1; o3[idx] = d2;
            } else if (epi == EPI_L2_SP) {
                float h, d1, d2; act_sp(v + bias[c], h, d1, d2);
                float w = w3[c]; o1[idx] = w * d1; o2[idx] = w * d2;
            } else if (epi == EPI_L2_Q) {
                float h, d1, d2; act_q(v + bias[c], h, d1, d2);
                float w = w3[c]; o1[idx] = w * d1; o2[idx] = w * d2;
            } else if (epi == EPI_V1) {
                o1[idx] = e1[idx] * v; o2[idx] = e2[idx] * v;
            } else if (epi == EPI_G_ST) {
                o1[idx] = v;
            } else {  // EPI_G_ADD
                o1[idx] += v;
            }
        }
    }
}

// ---------------- fused per-sample Hessian + solve kernel -------------------
// Thread tile mapping for F (64 rows x 256 cols), 256 threads:
//   ty = tid>>5 (8 row-groups of 8 rows), tx = tid&31.
//   Each thread owns rows ty*8..ty*8+7 and cols {tx*4..tx*4+3, 128+tx*4..+3}
//   (split-column mapping -> conflict-free LDS.128 on the B operand).
// smem layout (floats):
//   sW1T : [0, 16384)         W1^T [256][64]
//   sW2t : [16384, 24576)     scaled W2 k-tile [32][256]; later aliased:
//            sF  = +0    [32][64]   F column-chunk staged ([col][row])
//            sFb = +2048 [32][64]   F*b staged
//            sM  = +4096 [32][33]   augmented solve matrix
//   sP   : [24576, 24832)   p1
//   sAv  : [24832, 25088)   p2*v1
//   sBv  : [25088, 25344)   w3*phi''(z2)
//   sH   : [25344, 27424)   [32][65]  H rows 32:64
//   sQ   : 27424, sJ : 27456, sX : 27488   (32 each)
#define BIG_SMEM_FLOATS 27520

__global__ __launch_bounds__(256, 2)
void k_big(const float* __restrict__ x,
           const float* __restrict__ W2m, const float* __restrict__ W2q,
           float* __restrict__ out) {
    extern __shared__ float sm[];
    float* sW1T = sm;
    float* sW2t = sm + 16384;
    float* sF   = sW2t;
    float* sFb  = sW2t + 2048;
    float* sM   = sW2t + 4096;
    float* sP   = sm + 24576;
    float* sAv  = sm + 24832;
    float* sBv  = sm + 25088;
    float* sH   = sm + 25344;
    float* sQ   = sm + 27424;
    float* sJ   = sm + 27456;
    float* sX   = sm + 27488;

    int s   = blockIdx.x;
    int tid = threadIdx.x;
    int ty  = tid >> 5;          // 0..7 : 8-row group of F
    int tx  = tid & 31;          // 0..31: column group (split mapping)
    int hr  = (tid >> 5) * 4;    // H row group (H rows 32+hr .. 32+hr+3)
    int hc  = (tid & 31) * 2;    // H col group
    float Hacc[8] = {};

    for (int br = 0; br < 2; br++) {
        const float* W2  = br ? W2q : W2m;
        const float* w1t = g_W1T + br * (HH * DD);
#pragma unroll
        for (int i = 0; i < 16; i++) {
            int idx = (tid + i * 256) * 4;
            *(float4*)(sW1T + idx) = *(const float4*)(w1t + idx);
        }
        sP[tid]  = g_p1[br * BROFF + s * HH + tid];
        sAv[tid] = g_av[br * BROFF + s * HH + tid];
        sBv[tid] = g_bv[br * BROFF + s * HH + tid];
        __syncthreads();

        // ---- F = (W1 * diag(p1)) @ W2, 8x8 per thread in registers ----
        float acc[8][8] = {};
        for (int kt = 0; kt < 8; kt++) {
            // stage W2 k-tile scaled by p1
#pragma unroll
            for (int i = 0; i < 8; i++) {
                int v  = tid + i * 256;          // 2048 float4s
                int kk = v >> 6;
                int j4 = (v & 63) * 4;
                int k  = kt * 32 + kk;
                float4 w = *(const float4*)(W2 + (size_t)k * 256 + j4);
                float p = sP[k];
                w.x *= p; w.y *= p; w.z *= p; w.w *= p;
                *(float4*)(sW2t + kk * 256 + j4) = w;
            }
            __syncthreads();
#pragma unroll 8
            for (int kk = 0; kk < 32; kk++) {
                const float* w1row = sW1T + (kt * 32 + kk) * 64 + ty * 8;
                float4 a0 = *(const float4*)(w1row);
                float4 a1 = *(const float4*)(w1row + 4);
                const float* w2row = sW2t + kk * 256 + tx * 4;
                float4 b0 = *(const float4*)(w2row);         // cols tx*4..+3
                float4 b1 = *(const float4*)(w2row + 128);   // cols 128+tx*4..+3
                float a[8] = {a0.x, a0.y, a0.z, a0.w, a1.x, a1.y, a1.z, a1.w};
                float b[8] = {b0.x, b0.y, b0.z, b0.w, b1.x, b1.y, b1.z, b1.w};
#pragma unroll
                for (int r = 0; r < 8; r++)
#pragma unroll
                    for (int j = 0; j < 8; j++) acc[r][j] += a[r] * b[j];
            }
            __syncthreads();
        }

        // ---- H += F[32:64] diag(bv) F^T, in 8 column-chunks of 32 ----
        // chunk jc covers global cols half*128 + sub*32 .. +31,
        // half = jc>>2, sub = jc&3; owned by threads with tx>>3 == sub.
        for (int jc = 0; jc < 8; jc++) {
            int sub  = jc & 3;
            int half = jc >> 2;
            if ((tx >> 3) == sub) {
                int lc0 = (tx & 7) * 4;      // local col within chunk
                int jo  = half * 4;          // acc j-offset
#pragma unroll
                for (int jj = 0; jj < 4; jj++) {
                    float bc = sBv[half * 128 + sub * 32 + lc0 + jj];
#pragma unroll
                    for (int rr = 0; rr < 8; rr++) {
                        float f = acc[rr][jo + jj];
                        sF [(lc0 + jj) * 64 + ty * 8 + rr] = f;
                        sFb[(lc0 + jj) * 64 + ty * 8 + rr] = f * bc;
                    }
                }
            }
            __syncthreads();
#pragma unroll 4
            for (int jj = 0; jj < 32; jj++) {
                float4 fr = *(const float4*)(sF  + jj * 64 + 32 + hr);
                float2 fc = *(const float2*)(sFb + jj * 64 + hc);
                Hacc[0] += fr.x * fc.x; Hacc[1] += fr.x * fc.y;
                Hacc[2] += fr.y * fc.x; Hacc[3] += fr.y * fc.y;
                Hacc[4] += fr.z * fc.x; Hacc[5] += fr.z * fc.y;
                Hacc[6] += fr.w * fc.x; Hacc[7] += fr.w * fc.y;
            }
            __syncthreads();
        }

        // ---- H += W1 diag(av) W1^T (rows 32:64) ----
#pragma unroll 4
        for (int k = 0; k < 256; k++) {
            const float* row = sW1T + k * 64;
            float ak = sAv[k];
            float4 wr = *(const float4*)(row + 32 + hr);
            float2 wc = *(const float2*)(row + hc);
            float c0 = ak * wc.x, c1 = ak * wc.y;
            Hacc[0] += wr.x * c0; Hacc[1] += wr.x * c1;
            Hacc[2] += wr.y * c0; Hacc[3] += wr.y * c1;
            Hacc[4] += wr.z * c0; Hacc[5] += wr.z * c1;
            Hacc[6] += wr.w * c0; Hacc[7] += wr.w * c1;
        }
        __syncthreads();   // before next branch overwrites sW1T / vectors
    }

    // ---- stage H rows [32:64), add quad-term 2I on A diag ----
#pragma unroll
    for (int i = 0; i < 4; i++)
#pragma unroll
        for (int j = 0; j < 2; j++) {
            int r = hr + i, c = hc + j;
            float v = Hacc[i * 2 + j];
            if (c == 32 + r) v += 2.0f;
            sH[r * 65 + c] = v;
        }
    if (tid < 32) {
        sQ[tid] = x[(size_t)s * 64 + 32 + tid];
        sJ[tid] = g_jl[(size_t)s * 64 + tid];
    }
    __syncthreads();

    // ---- build augmented system: A = H[:,32:64]+2I, rhs = jac - B qdot ----
    if (tid < 32) {
        float rhs = sJ[tid];
        for (int c = 0; c < 32; c++) rhs -= sH[tid * 65 + c] * sQ[c];
        for (int j = 0; j < 32; j++) sM[tid * 33 + j] = sH[tid * 65 + 32 + j];
        sM[tid * 33 + 32] = rhs;
    }
    __syncthreads();

    // ---- Gaussian elimination with partial pivoting (warp 0) ----
    if (tid < 32) {
        int lane = tid;
        for (int k = 0; k < 32; k++) {
            float v = (lane >= k) ? fabsf(sM[lane * 33 + k]) : -1.0f;
            int p = lane;
#pragma unroll
            for (int off = 16; off; off >>= 1) {
                float v2 = __shfl_xor_sync(0xffffffffu, v, off);
                int   p2 = __shfl_xor_sync(0xffffffffu, p, off);
                if (v2 > v || (v2 == v && p2 < p)) { v = v2; p = p2; }
            }
            if (p != k) {
                float a = sM[k * 33 + lane], b = sM[p * 33 + lane];
                sM[k * 33 + lane] = b; sM[p * 33 + lane] = a;
                if (lane == 0) {
                    float a2 = sM[k * 33 + 32], b2 = sM[p * 33 + 32];
                    sM[k * 33 + 32] = b2; sM[p * 33 + 32] = a2;
                }
            }
            __syncwarp();
            if (lane > k) {
                float f = sM[lane * 33 + k] / sM[k * 33 + k];
                for (int c = k; c <= 32; c++) sM[lane * 33 + c] -= f * sM[k * 33 + c];
            }
            __syncwarp();
        }
        // back substitution
        float accv = 0.0f;
        for (int k = 31; k >= 0; k--) {
            float xk = 0.0f;
            if (lane == k) xk = (sM[k * 33 + 32] - accv) / sM[k * 33 + k];
            xk = __shfl_sync(0xffffffffu, xk, k);
            if (lane < k) accv += sM[lane * 33 + k] * xk;
            if (lane == k) sX[k] = xk;
        }
    }
    __syncthreads();
    if (tid < 64) out[(size_t)s * 64 + tid] = (tid < 32) ? sQ[tid] : sX[tid - 32];
}

// ---------------- host ------------------------------------------------------
extern "C" void kernel_launch(void* const* d_in, const int* in_sizes, int n_in,
                              void* d_out, int out_size) {
    const float* x   = (const float*)d_in[0];
    const float* mW1 = (const float*)d_in[1];
    const float* mb1 = (const float*)d_in[2];
    const float* mW2 = (const float*)d_in[3];
    const float* mb2 = (const float*)d_in[4];
    const float* mW3 = (const float*)d_in[5];
    const float* qW1 = (const float*)d_in[6];
    const float* qb1 = (const float*)d_in[7];
    const float* qW2 = (const float*)d_in[8];
    const float* qb2 = (const float*)d_in[9];
    const float* qW3 = (const float*)d_in[10];
    float* out = (float*)d_out;

    float *h1, *p1, *p2, *u2, *bv, *wv, *av, *jl, *w1t, *w2t;
    cudaGetSymbolAddress((void**)&h1,  g_h1);
    cudaGetSymbolAddress((void**)&p1,  g_p1);
    cudaGetSymbolAddress((void**)&p2,  g_p2);
    cudaGetSymbolAddress((void**)&u2,  g_u2);
    cudaGetSymbolAddress((void**)&bv,  g_bv);
    cudaGetSymbolAddress((void**)&wv,  g_wv);
    cudaGetSymbolAddress((void**)&av,  g_av);
    cudaGetSymbolAddress((void**)&jl,  g_jl);
    cudaGetSymbolAddress((void**)&w1t, g_W1T);
    cudaGetSymbolAddress((void**)&w2t, g_W2T);

    cudaFuncSetAttribute(k_big, cudaFuncAttributeMaxDynamicSharedMemorySize,
                         BIG_SMEM_FLOATS * 4);

    k_transpose<<<640, 256>>>(mW1, qW1, mW2, qW2);

    dim3 g256(64, 4), g64(64, 1);
    for (int br = 0; br < 2; br++) {
        const float* W1 = br ? qW1 : mW1;
        const float* b1 = br ? qb1 : mb1;
        const float* W2 = br ? qW2 : mW2;
        const float* b2 = br ? qb2 : mb2;
        const float* W3 = br ? qW3 : mW3;
        size_t off = (size_t)br * BROFF;

        // z1 = x@W1+b1 -> h1, p1=a'(z1), p2=a''(z1)
        k_gemm<<<g256, 256>>>(x, W1, 64, 256, br ? EPI_L1_Q : EPI_L1_SP,
                              b1, nullptr, nullptr, nullptr,
                              h1 + off, p1 + off, p2 + off);
        // z2 = h1@W2+b2 -> u2=w3*a'(z2), bv=w3*a''(z2)
        k_gemm<<<g256, 256>>>(h1 + off, W2, 256, 256, br ? EPI_L2_Q : EPI_L2_SP,
                              b2, W3, nullptr, nullptr,
                              u2 + off, bv + off, nullptr);
        // v1 = u2@W2^T -> wv=p1*v1, av=p2*v1
        k_gemm<<<g256, 256>>>(u2 + off, w2t + (size_t)br * 65536, 256, 256, EPI_V1,
                              nullptr, nullptr, p1 + off, p2 + off,
                              wv + off, av + off, nullptr);
        // jac += wv@W1^T
        k_gemm<<<g64, 256>>>(wv + off, w1t + (size_t)br * 16384, 256, 64,
                             br ? EPI_G_ADD : EPI_G_ST,
                             nullptr, nullptr, nullptr, nullptr,
                             jl, nullptr, nullptr);
    }

    k_big<<<BSZ, 256, BIG_SMEM_FLOATS * 4>>>(x, mW2, qW2, out);
}

// round 6
// speedup vs baseline: 1.0925x; 1.0925x over previous
#include <cuda_runtime.h>
#include <math.h>

#define BSZ 4096
#define DD  64
#define HH  256
#define NN  32
#define BROFF (BSZ * HH)

typedef unsigned long long ull;

// ---------------- scratch (device globals; no allocation allowed) ----------
__device__ float g_h1[2 * BSZ * HH];
__device__ float g_p1[2 * BSZ * HH];
__device__ float g_p2[2 * BSZ * HH];
__device__ float g_u2[2 * BSZ * HH];
__device__ float g_bv[2 * BSZ * HH];
__device__ float g_wv[2 * BSZ * HH];
__device__ float g_av[2 * BSZ * HH];
__device__ float g_jl[BSZ * DD];
__device__ float g_W1T[2 * HH * DD];   // [k][r]  (256x64 per branch)
__device__ float g_W2T[2 * HH * HH];   // [j][i]  (256x256 per branch)

// ---------------- packed f32x2 helpers --------------------------------------
__device__ __forceinline__ void ffma2(ull& acc, ull a, ull b) {
    asm("fma.rn.f32x2 %0, %1, %2, %0;" : "+l"(acc) : "l"(a), "l"(b));
}
__device__ __forceinline__ ull packdup(float v) {
    ull r; unsigned u = __float_as_uint(v);
    asm("mov.b64 %0, {%1, %1};" : "=l"(r) : "r"(u));
    return r;
}
__device__ __forceinline__ void unpack2(ull v, float& lo, float& hi) {
    unsigned a, b;
    asm("mov.b64 {%0, %1}, %2;" : "=r"(a), "=r"(b) : "l"(v));
    lo = __uint_as_float(a); hi = __uint_as_float(b);
}

// ---------------- activations ----------------------------------------------
__device__ __forceinline__ void act_sp(float z, float& h, float& d1, float& d2) {
    float s = 1.0f / (1.0f + expf(-z));
    h  = fmaxf(z, 0.0f) + log1pf(expf(-fabsf(z)));
    d1 = s;
    d2 = s * (1.0f - s);
}
__device__ __forceinline__ void act_q(float z, float& h, float& d1, float& d2) {
    // phi(z) = z*tanh(0.5 z)
    float t = tanhf(0.5f * z);
    float c = 1.0f - t * t;
    h  = z * t;
    d1 = t + 0.5f * z * c;
    d2 = c * (1.0f - 0.5f * z * t);
}

// ---------------- transpose helper ------------------------------------------
__global__ void k_transpose(const float* __restrict__ W1m, const float* __restrict__ W1q,
                            const float* __restrict__ W2m, const float* __restrict__ W2q) {
    int tid = blockIdx.x * blockDim.x + threadIdx.x;
    if (tid < 16384) {
        int r = tid / 256, k = tid % 256;
        g_W1T[k * 64 + r] = W1m[tid];
    } else if (tid < 32768) {
        int t = tid - 16384; int r = t / 256, k = t % 256;
        g_W1T[16384 + k * 64 + r] = W1q[t];
    } else if (tid < 98304) {
        int t = tid - 32768; int i = t / 256, j = t % 256;
        g_W2T[j * 256 + i] = W2m[t];
    } else if (tid < 163840) {
        int t = tid - 98304; int i = t / 256, j = t % 256;
        g_W2T[65536 + j * 256 + i] = W2q[t];
    }
}

// ---------------- generic 64x64-tile GEMM with fused epilogues --------------
#define EPI_L1_SP 0
#define EPI_L1_Q  1
#define EPI_L2_SP 2
#define EPI_L2_Q  3
#define EPI_V1    4
#define EPI_G_ST  5
#define EPI_G_ADD 6

__global__ __launch_bounds__(256)
void k_gemm(const float* __restrict__ A, const float* __restrict__ Bm,
            int K, int N, int epi,
            const float* __restrict__ bias, const float* __restrict__ w3,
            const float* __restrict__ e1, const float* __restrict__ e2,
            float* __restrict__ o1, float* __restrict__ o2, float* __restrict__ o3) {
    __shared__ float sA[16][65];
    __shared__ float sB[16][64];
    int tid = threadIdx.x;
    int bm = blockIdx.x * 64, bn = blockIdx.y * 64;
    int ty = tid >> 4, tx = tid & 15;
    int ar = tid >> 2, akq = (tid & 3) * 4;
    int bk = tid >> 4, bnq = (tid & 15) * 4;
    float acc[4][4] = {};
    for (int k0 = 0; k0 < K; k0 += 16) {
        float4 av = *(const float4*)(A + (size_t)(bm + ar) * K + k0 + akq);
        sA[akq + 0][ar] = av.x; sA[akq + 1][ar] = av.y;
        sA[akq + 2][ar] = av.z; sA[akq + 3][ar] = av.w;
        *(float4*)(&sB[bk][bnq]) = *(const float4*)(Bm + (size_t)(k0 + bk) * N + bn + bnq);
        __syncthreads();
#pragma unroll
        for (int kk = 0; kk < 16; kk++) {
            float a[4], b[4];
#pragma unroll
            for (int i = 0; i < 4; i++) a[i] = sA[kk][ty * 4 + i];
#pragma unroll
            for (int j = 0; j < 4; j++) b[j] = sB[kk][tx * 4 + j];
#pragma unroll
            for (int i = 0; i < 4; i++)
#pragma unroll
                for (int j = 0; j < 4; j++) acc[i][j] += a[i] * b[j];
        }
        __syncthreads();
    }
#pragma unroll
    for (int i = 0; i < 4; i++) {
        int s = bm + ty * 4 + i;
#pragma unroll
        for (int j = 0; j < 4; j++) {
            int c = bn + tx * 4 + j;
            float v = acc[i][j];
            size_t idx = (size_t)s * N + c;
            if (epi == EPI_L1_SP) {
                float h, d1, d2; act_sp(v + bias[c], h, d1, d2);
                o1[idx] = h; o2[idx] = d1; o3[idx] = d2;
            } else if (epi == EPI_L1_Q) {
                float h, d1, d2; act_q(v + bias[c], h, d1, d2);
                o1[idx] = h; o2[idx] = d1; o3[idx] = d2;
            } else if (epi == EPI_L2_SP) {
                float h, d1, d2; act_sp(v + bias[c], h, d1, d2);
                float w = w3[c]; o1[idx] = w * d1; o2[idx] = w * d2;
            } else if (epi == EPI_L2_Q) {
                float h, d1, d2; act_q(v + bias[c], h, d1, d2);
                float w = w3[c]; o1[idx] = w * d1; o2[idx] = w * d2;
            } else if (epi == EPI_V1) {
                o1[idx] = e1[idx] * v; o2[idx] = e2[idx] * v;
            } else if (epi == EPI_G_ST) {
                o1[idx] = v;
            } else {  // EPI_G_ADD
                o1[idx] += v;
            }
        }
    }
}

// ---------------- fused per-sample Hessian + solve kernel -------------------
// F (64x256) per sample; 256 threads; ty=tid>>5 owns rows ty*8..+7 (as 4 row
// PAIRS, packed f32x2), tx=tid&31 owns cols {tx*4..+3, 128+tx*4..+3}.
#define BIG_SMEM_FLOATS 27520

__global__ __launch_bounds__(256, 2)
void k_big(const float* __restrict__ x,
           const float* __restrict__ W2m, const float* __restrict__ W2q,
           float* __restrict__ out) {
    extern __shared__ float sm[];
    float* sW1T = sm;
    float* sW2t = sm + 16384;
    float* sF   = sW2t;
    float* sFb  = sW2t + 2048;
    float* sM   = sW2t + 4096;
    float* sP   = sm + 24576;
    float* sAv  = sm + 24832;
    float* sBv  = sm + 25088;
    float* sH   = sm + 25344;
    float* sQ   = sm + 27424;
    float* sJ   = sm + 27456;
    float* sX   = sm + 27488;

    int s   = blockIdx.x;
    int tid = threadIdx.x;
    int ty  = tid >> 5;          // 0..7 : 8-row group of F
    int tx  = tid & 31;          // 0..31: column group (split mapping)
    int hr  = (tid >> 5) * 4;    // H row group (H rows 32+hr .. 32+hr+3)
    int hc  = (tid & 31) * 2;    // H col group
    // packed H accumulators: Hp[rp][j] holds rows (hr+2rp, hr+2rp+1), col hc+j
    ull Hp[2][2] = {{0ull, 0ull}, {0ull, 0ull}};

    for (int br = 0; br < 2; br++) {
        const float* W2  = br ? W2q : W2m;
        const float* w1t = g_W1T + br * (HH * DD);
#pragma unroll
        for (int i = 0; i < 16; i++) {
            int idx = (tid + i * 256) * 4;
            *(float4*)(sW1T + idx) = *(const float4*)(w1t + idx);
        }
        sP[tid]  = g_p1[br * BROFF + s * HH + tid];
        sAv[tid] = g_av[br * BROFF + s * HH + tid];
        sBv[tid] = g_bv[br * BROFF + s * HH + tid];
        __syncthreads();

        // ---- F = (W1 * diag(p1)) @ W2 : packed f32x2, 4 row-pairs x 8 cols --
        ull accp[4][8];
#pragma unroll
        for (int rp = 0; rp < 4; rp++)
#pragma unroll
            for (int j = 0; j < 8; j++) accp[rp][j] = 0ull;

        for (int kt = 0; kt < 8; kt++) {
            // stage W2 k-tile scaled by p1
#pragma unroll
            for (int i = 0; i < 8; i++) {
                int v  = tid + i * 256;          // 2048 float4s
                int kk = v >> 6;
                int j4 = (v & 63) * 4;
                int k  = kt * 32 + kk;
                float4 w = *(const float4*)(W2 + (size_t)k * 256 + j4);
                float p = sP[k];
                w.x *= p; w.y *= p; w.z *= p; w.w *= p;
                *(float4*)(sW2t + kk * 256 + j4) = w;
            }
            __syncthreads();
#pragma unroll 8
            for (int kk = 0; kk < 32; kk++) {
                const float* w1row = sW1T + (kt * 32 + kk) * 64 + ty * 8;
                ull ap[4];
                ap[0] = *(const ull*)(w1row);
                ap[1] = *(const ull*)(w1row + 2);
                ap[2] = *(const ull*)(w1row + 4);
                ap[3] = *(const ull*)(w1row + 6);
                const float* w2row = sW2t + kk * 256 + tx * 4;
                float4 b0 = *(const float4*)(w2row);         // cols tx*4..+3
                float4 b1 = *(const float4*)(w2row + 128);   // cols 128+tx*4..+3
                ull bd[8];
                bd[0] = packdup(b0.x); bd[1] = packdup(b0.y);
                bd[2] = packdup(b0.z); bd[3] = packdup(b0.w);
                bd[4] = packdup(b1.x); bd[5] = packdup(b1.y);
                bd[6] = packdup(b1.z); bd[7] = packdup(b1.w);
#pragma unroll
                for (int rp = 0; rp < 4; rp++)
#pragma unroll
                    for (int j = 0; j < 8; j++) ffma2(accp[rp][j], ap[rp], bd[j]);
            }
            __syncthreads();
        }

        // ---- H += F[32:64] diag(bv) F^T, in 8 column-chunks of 32 ----
        for (int jc = 0; jc < 8; jc++) {
            int sub  = jc & 3;
            int half = jc >> 2;
            if ((tx >> 3) == sub) {
                int lc0 = (tx & 7) * 4;      // local col within chunk
                int jo  = half * 4;          // acc j-offset
#pragma unroll
                for (int jj = 0; jj < 4; jj++) {
                    float bc = sBv[half * 128 + sub * 32 + lc0 + jj];
#pragma unroll
                    for (int rp = 0; rp < 4; rp++) {
                        float f0, f1; unpack2(accp[rp][jo + jj], f0, f1);
                        int rbase = (lc0 + jj) * 64 + ty * 8 + rp * 2;
                        sF [rbase]     = f0;       sF [rbase + 1] = f1;
                        sFb[rbase]     = f0 * bc;  sFb[rbase + 1] = f1 * bc;
                    }
                }
            }
            __syncthreads();
#pragma unroll 4
            for (int jj = 0; jj < 32; jj++) {
                ull fr01 = *(const ull*)(sF + jj * 64 + 32 + hr);
                ull fr23 = *(const ull*)(sF + jj * 64 + 34 + hr);
                float2 fc = *(const float2*)(sFb + jj * 64 + hc);
                ull fcx = packdup(fc.x), fcy = packdup(fc.y);
                ffma2(Hp[0][0], fr01, fcx); ffma2(Hp[0][1], fr01, fcy);
                ffma2(Hp[1][0], fr23, fcx); ffma2(Hp[1][1], fr23, fcy);
            }
            __syncthreads();
        }

        // ---- H += W1 diag(av) W1^T (rows 32:64) ----
#pragma unroll 4
        for (int k = 0; k < 256; k++) {
            const float* row = sW1T + k * 64;
            float ak = sAv[k];
            ull wr01 = *(const ull*)(row + 32 + hr);
            ull wr23 = *(const ull*)(row + 34 + hr);
            float2 wc = *(const float2*)(row + hc);
            ull c0 = packdup(ak * wc.x), c1 = packdup(ak * wc.y);
            ffma2(Hp[0][0], wr01, c0); ffma2(Hp[0][1], wr01, c1);
            ffma2(Hp[1][0], wr23, c0); ffma2(Hp[1][1], wr23, c1);
        }
        __syncthreads();   // before next branch overwrites sW1T / vectors
    }

    // ---- stage H rows [32:64), add quad-term 2I on A diag ----
#pragma unroll
    for (int rp = 0; rp < 2; rp++)
#pragma unroll
        for (int j = 0; j < 2; j++) {
            float f0, f1; unpack2(Hp[rp][j], f0, f1);
            int r0 = hr + 2 * rp, c = hc + j;
            if (c == 32 + r0)     f0 += 2.0f;
            if (c == 32 + r0 + 1) f1 += 2.0f;
            sH[r0 * 65 + c]       = f0;
            sH[(r0 + 1) * 65 + c] = f1;
        }
    if (tid < 32) {
        sQ[tid] = x[(size_t)s * 64 + 32 + tid];
        sJ[tid] = g_jl[(size_t)s * 64 + tid];
    }
    __syncthreads();

    // ---- build augmented system: A = H[:,32:64]+2I, rhs = jac - B qdot ----
    if (tid < 32) {
        float rhs = sJ[tid];
        for (int c = 0; c < 32; c++) rhs -= sH[tid * 65 + c] * sQ[c];
        for (int j = 0; j < 32; j++) sM[tid * 33 + j] = sH[tid * 65 + 32 + j];
        sM[tid * 33 + 32] = rhs;
    }
    __syncthreads();

    // ---- Gaussian elimination with partial pivoting (warp 0) ----
    if (tid < 32) {
        int lane = tid;
        for (int k = 0; k < 32; k++) {
            float v = (lane >= k) ? fabsf(sM[lane * 33 + k]) : -1.0f;
            int p = lane;
#pragma unroll
            for (int off = 16; off; off >>= 1) {
                float v2 = __shfl_xor_sync(0xffffffffu, v, off);
                int   p2 = __shfl_xor_sync(0xffffffffu, p, off);
                if (v2 > v || (v2 == v && p2 < p)) { v = v2; p = p2; }
            }
            if (p != k) {
                float a = sM[k * 33 + lane], b = sM[p * 33 + lane];
                sM[k * 33 + lane] = b; sM[p * 33 + lane] = a;
                if (lane == 0) {
                    float a2 = sM[k * 33 + 32], b2 = sM[p * 33 + 32];
                    sM[k * 33 + 32] = b2; sM[p * 33 + 32] = a2;
                }
            }
            __syncwarp();
            if (lane > k) {
                float f = sM[lane * 33 + k] / sM[k * 33 + k];
                for (int c = k; c <= 32; c++) sM[lane * 33 + c] -= f * sM[k * 33 + c];
            }
            __syncwarp();
        }
        // back substitution
        float accv = 0.0f;
        for (int k = 31; k >= 0; k--) {
            float xk = 0.0f;
            if (lane == k) xk = (sM[k * 33 + 32] - accv) / sM[k * 33 + k];
            xk = __shfl_sync(0xffffffffu, xk, k);
            if (lane < k) accv += sM[lane * 33 + k] * xk;
            if (lane == k) sX[k] = xk;
        }
    }
    __syncthreads();
    if (tid < 64) out[(size_t)s * 64 + tid] = (tid < 32) ? sQ[tid] : sX[tid - 32];
}

// ---------------- host ------------------------------------------------------
extern "C" void kernel_launch(void* const* d_in, const int* in_sizes, int n_in,
                              void* d_out, int out_size) {
    const float* x   = (const float*)d_in[0];
    const float* mW1 = (const float*)d_in[1];
    const float* mb1 = (const float*)d_in[2];
    const float* mW2 = (const float*)d_in[3];
    const float* mb2 = (const float*)d_in[4];
    const float* mW3 = (const float*)d_in[5];
    const float* qW1 = (const float*)d_in[6];
    const float* qb1 = (const float*)d_in[7];
    const float* qW2 = (const float*)d_in[8];
    const float* qb2 = (const float*)d_in[9];
    const float* qW3 = (const float*)d_in[10];
    float* out = (float*)d_out;

    float *h1, *p1, *p2, *u2, *bv, *wv, *av, *jl, *w1t, *w2t;
    cudaGetSymbolAddress((void**)&h1,  g_h1);
    cudaGetSymbolAddress((void**)&p1,  g_p1);
    cudaGetSymbolAddress((void**)&p2,  g_p2);
    cudaGetSymbolAddress((void**)&u2,  g_u2);
    cudaGetSymbolAddress((void**)&bv,  g_bv);
    cudaGetSymbolAddress((void**)&wv,  g_wv);
    cudaGetSymbolAddress((void**)&av,  g_av);
    cudaGetSymbolAddress((void**)&jl,  g_jl);
    cudaGetSymbolAddress((void**)&w1t, g_W1T);
    cudaGetSymbolAddress((void**)&w2t, g_W2T);

    cudaFuncSetAttribute(k_big, cudaFuncAttributeMaxDynamicSharedMemorySize,
                         BIG_SMEM_FLOATS * 4);

    k_transpose<<<640, 256>>>(mW1, qW1, mW2, qW2);

    dim3 g256(64, 4), g64(64, 1);
    for (int br = 0; br < 2; br++) {
        const float* W1 = br ? qW1 : mW1;
        const float* b1 = br ? qb1 : mb1;
        const float* W2 = br ? qW2 : mW2;
        const float* b2 = br ? qb2 : mb2;
        const float* W3 = br ? qW3 : mW3;
        size_t off = (size_t)br * BROFF;

        // z1 = x@W1+b1 -> h1, p1=a'(z1), p2=a''(z1)
        k_gemm<<<g256, 256>>>(x, W1, 64, 256, br ? EPI_L1_Q : EPI_L1_SP,
                              b1, nullptr, nullptr, nullptr,
                              h1 + off, p1 + off, p2 + off);
        // z2 = h1@W2+b2 -> u2=w3*a'(z2), bv=w3*a''(z2)
        k_gemm<<<g256, 256>>>(h1 + off, W2, 256, 256, br ? EPI_L2_Q : EPI_L2_SP,
                              b2, W3, nullptr, nullptr,
                              u2 + off, bv + off, nullptr);
        // v1 = u2@W2^T -> wv=p1*v1, av=p2*v1
        k_gemm<<<g256, 256>>>(u2 + off, w2t + (size_t)br * 65536, 256, 256, EPI_V1,
                              nullptr, nullptr, p1 + off, p2 + off,
                              wv + off, av + off, nullptr);
        // jac += wv@W1^T
        k_gemm<<<g64, 256>>>(wv + off, w1t + (size_t)br * 16384, 256, 64,
                             br ? EPI_G_ADD : EPI_G_ST,
                             nullptr, nullptr, nullptr, nullptr,
                             jl, nullptr, nullptr);
    }

    k_big<<<BSZ, 256, BIG_SMEM_FLOATS * 4>>>(x, mW2, qW2, out);
}

// round 11
// speedup vs baseline: 2.0349x; 1.8625x over previous
#include <cuda_runtime.h>
#include <cuda_bf16.h>
#include <math.h>

#define BSZ 4096
#define DD  64
#define HH  256
#define BROFF (BSZ * HH)

typedef unsigned long long ull;

// ---------------- scratch (device globals) ----------------------------------
__device__ float g_h1[2 * BSZ * HH];
__device__ float g_p1[2 * BSZ * HH];
__device__ float g_p2[2 * BSZ * HH];
__device__ float g_u2[2 * BSZ * HH];
__device__ float g_bv[2 * BSZ * HH];
__device__ float g_wv[2 * BSZ * HH];
__device__ float g_av[2 * BSZ * HH];
__device__ float g_jl[BSZ * DD];
__device__ float g_W1T[2 * HH * DD];            // [k][r] per branch
__device__ float g_W2T[2 * HH * HH];            // [j][i] per branch
// W2^T bf16 hi/lo, [br][split][n][k], k quad-permuted per 16-group for LDS.64 frags
__device__ unsigned short g_BW2[2 * 2 * 65536];

// ---------------- packed f32x2 helpers ---------------------------------------
__device__ __forceinline__ void ffma2(ull& acc, ull a, ull b) {
    asm("fma.rn.f32x2 %0, %1, %2, %0;" : "+l"(acc) : "l"(a), "l"(b));
}
__device__ __forceinline__ ull packdup(float v) {
    ull r; unsigned u = __float_as_uint(v);
    asm("mov.b64 %0, {%1, %1};" : "=l"(r) : "r"(u));
    return r;
}
__device__ __forceinline__ void unpack2(ull v, float& lo, float& hi) {
    unsigned a, b;
    asm("mov.b64 {%0, %1}, %2;" : "=r"(a), "=r"(b) : "l"(v));
    lo = __uint_as_float(a); hi = __uint_as_float(b);
}

// ---------------- warp mma (sm_80 baseline; no arch 'a' feature) -------------
#define MMA_BF16(d, a0, a1, a2, a3, b0, b1) \
    asm volatile("mma.sync.aligned.m16n8k16.row.col.f32.bf16.bf16.f32 " \
        "{%0,%1,%2,%3}, {%4,%5,%6,%7}, {%8,%9}, {%0,%1,%2,%3};" \
        : "+f"((d)[0]), "+f"((d)[1]), "+f"((d)[2]), "+f"((d)[3]) \
        : "r"(a0), "r"(a1), "r"(a2), "r"(a3), "r"(b0), "r"(b1))

// ---------------- activations ------------------------------------------------
__device__ __forceinline__ void act_sp(float z, float& h, float& d1, float& d2) {
    float s = 1.0f / (1.0f + expf(-z));
    h  = fmaxf(z, 0.0f) + log1pf(expf(-fabsf(z)));
    d1 = s;
    d2 = s * (1.0f - s);
}
__device__ __forceinline__ void act_q(float z, float& h, float& d1, float& d2) {
    float t = tanhf(0.5f * z);
    float c = 1.0f - t * t;
    h  = z * t;
    d1 = t + 0.5f * z * c;
    d2 = c * (1.0f - 0.5f * z * t);
}

// ---------------- prep: transposes -------------------------------------------
__global__ void k_transpose(const float* __restrict__ W1m, const float* __restrict__ W1q,
                            const float* __restrict__ W2m, const float* __restrict__ W2q) {
    int tid = blockIdx.x * blockDim.x + threadIdx.x;
    if (tid < 16384) {
        int r = tid / 256, k = tid % 256;
        g_W1T[k * 64 + r] = W1m[tid];
    } else if (tid < 32768) {
        int t = tid - 16384; int r = t / 256, k = t % 256;
        g_W1T[16384 + k * 64 + r] = W1q[t];
    } else if (tid < 98304) {
        int t = tid - 32768; int i = t / 256, j = t % 256;
        g_W2T[j * 256 + i] = W2m[t];
    } else if (tid < 163840) {
        int t = tid - 98304; int i = t / 256, j = t % 256;
        g_W2T[65536 + j * 256 + i] = W2q[t];
    }
}

// ---------------- prep: W2^T bf16 hi/lo with k-quad permutation ----------------
// storage quad t of each 16-k group holds logical k {2t, 2t+1, 2t+8, 2t+9}
__global__ void k_prepB(const float* __restrict__ W2m, const float* __restrict__ W2q) {
    int t = blockIdx.x * blockDim.x + threadIdx.x;
    if (t >= 131072) return;
    int br = t >> 16;
    int e  = t & 65535;
    int k = e >> 8, n = e & 255;
    float v = (br ? W2q : W2m)[k * 256 + n];
    __nv_bfloat16 hb = __float2bfloat16_rn(v);
    __nv_bfloat16 lb = __float2bfloat16_rn(v - __bfloat162float(hb));
    int o = k & 15;
    int pos = (o < 8) ? (((o >> 1) << 2) | (o & 1))
                      : ((((o - 8) >> 1) << 2) + 2 + (o & 1));
    int kk = (k & ~15) + pos;
    g_BW2[((size_t)(br * 2 + 0) * 256 + n) * 256 + kk] = __bfloat16_as_ushort(hb);
    g_BW2[((size_t)(br * 2 + 1) * 256 + n) * 256 + kk] = __bfloat16_as_ushort(lb);
}

// ---------------- small GEMM with fused epilogues -----------------------------
#define EPI_L1_SP 0
#define EPI_L1_Q  1
#define EPI_L2_SP 2
#define EPI_L2_Q  3
#define EPI_V1    4
#define EPI_G_ST  5
#define EPI_G_ADD 6

__global__ __launch_bounds__(256)
void k_gemm(const float* __restrict__ A, const float* __restrict__ Bm,
            int K, int N, int epi,
            const float* __restrict__ bias, const float* __restrict__ w3,
            const float* __restrict__ e1, const float* __restrict__ e2,
            float* __restrict__ o1, float* __restrict__ o2, float* __restrict__ o3) {
    __shared__ float sA[16][65];
    __shared__ float sB[16][64];
    int tid = threadIdx.x;
    int bm = blockIdx.x * 64, bn = blockIdx.y * 64;
    int ty = tid >> 4, tx = tid & 15;
    int ar = tid >> 2, akq = (tid & 3) * 4;
    int bk = tid >> 4, bnq = (tid & 15) * 4;
    float acc[4][4] = {};
    for (int k0 = 0; k0 < K; k0 += 16) {
        float4 av = *(const float4*)(A + (size_t)(bm + ar) * K + k0 + akq);
        sA[akq + 0][ar] = av.x; sA[akq + 1][ar] = av.y;
        sA[akq + 2][ar] = av.z; sA[akq + 3][ar] = av.w;
        *(float4*)(&sB[bk][bnq]) = *(const float4*)(Bm + (size_t)(k0 + bk) * N + bn + bnq);
        __syncthreads();
#pragma unroll
        for (int kk = 0; kk < 16; kk++) {
            float a[4], b[4];
#pragma unroll
            for (int i = 0; i < 4; i++) a[i] = sA[kk][ty * 4 + i];
#pragma unroll
            for (int j = 0; j < 4; j++) b[j] = sB[kk][tx * 4 + j];
#pragma unroll
            for (int i = 0; i < 4; i++)
#pragma unroll
                for (int j = 0; j < 4; j++) acc[i][j] += a[i] * b[j];
        }
        __syncthreads();
    }
#pragma unroll
    for (int i = 0; i < 4; i++) {
        int s = bm + ty * 4 + i;
#pragma unroll
        for (int j = 0; j < 4; j++) {
            int c = bn + tx * 4 + j;
            float v = acc[i][j];
            size_t idx = (size_t)s * N + c;
            if (epi == EPI_L1_SP) {
                float h, d1, d2; act_sp(v + bias[c], h, d1, d2);
                o1[idx] = h; o2[idx] = d1; o3[idx] = d2;
            } else if (epi == EPI_L1_Q) {
                float h, d1, d2; act_q(v + bias[c], h, d1, d2);
                o1[idx] = h; o2[idx] = d1; o3[idx] = d2;
            } else if (epi == EPI_L2_SP) {
                float h, d1, d2; act_sp(v + bias[c], h, d1, d2);
                float w = w3[c]; o1[idx] = w * d1; o2[idx] = w * d2;
            } else if (epi == EPI_L2_Q) {
                float h, d1, d2; act_q(v + bias[c], h, d1, d2);
                float w = w3[c]; o1[idx] = w * d1; o2[idx] = w * d2;
            } else if (epi == EPI_V1) {
                o1[idx] = e1[idx] * v; o2[idx] = e2[idx] * v;
            } else if (epi == EPI_G_ST) {
                o1[idx] = v;
            } else {
                o1[idx] += v;
            }
        }
    }
}

// ---------------- fused mma.sync Hessian + solve kernel -----------------------
// One CTA = one sample pair (M = 128 F rows), 512 threads / 16 warps.
// warp w: rowtile = w&7 (rows rowtile*16..+15), nhalf = w>>3 (cols nhalf*128..+127)
// smem byte offsets:
#define OFF_W1T 0        // 65536  fp32 W1^T [k][r]
#define OFF_A   65536    // 40960  A slab: 128 rows x 80 k-ushort; hi +0, lo +20480
#define OFF_B   106496   // 81920  B slab: 256 n x 80 k-ushort; hi +0, lo +40960
                          // aliases on OFF_B region (phase-disjoint):
#define OFF_G   106496   //   33792  fp32 G scratch 128 x 66
#define OFF_FC  106496   //   16896  F chunk  [j][row] 32 x 132 fp32
#define OFF_FCB 123392   //   16896  F*b chunk
#define OFF_M   140288   //   8448   solve matrices 2 x 32 x 33
#define OFF_H   188416   // 16640  sH 2 x 32 x 65
#define OFF_P   205056   // 2048
#define OFF_AV  207104   // 2048
#define OFF_BV  209152   // 2048
#define OFF_Q   211200   // 256
#define OFF_J   211456   // 256
#define OFF_X   211712   // 256
#define SMEM_BYTES 211968

__global__ __launch_bounds__(512, 1)
void k_big(const float* __restrict__ x, float* __restrict__ out) {
    extern __shared__ char smc[];
    float* sW1T = (float*)(smc + OFF_W1T);
    unsigned short* sAhi = (unsigned short*)(smc + OFF_A);
    unsigned short* sAlo = sAhi + 10240;
    unsigned short* sBhi = (unsigned short*)(smc + OFF_B);
    unsigned short* sBlo = sBhi + 20480;
    float* sG   = (float*)(smc + OFF_G);
    float* sFc  = (float*)(smc + OFF_FC);
    float* sFcb = (float*)(smc + OFF_FCB);
    float* sM   = (float*)(smc + OFF_M);
    float* sH   = (float*)(smc + OFF_H);
    float* sPb  = (float*)(smc + OFF_P);
    float* sAvv = (float*)(smc + OFF_AV);
    float* sBvv = (float*)(smc + OFF_BV);
    float* sQ   = (float*)(smc + OFF_Q);
    float* sJ   = (float*)(smc + OFF_J);
    float* sX   = (float*)(smc + OFF_X);

    int tid  = threadIdx.x;
    int lane = tid & 31;
    int wid  = tid >> 5;
    int g    = lane >> 2;          // mma group
    int tq   = lane & 3;           // mma thread-in-group
    int rowtile = wid & 7;
    int nhalf   = wid >> 3;
    int s0  = blockIdx.x * 2;

    // H mapping (per 256-thread half = one sample)
    int sel = tid >> 8;
    int hr  = ((tid >> 5) & 7) * 4;
    int hc  = (tid & 31) * 2;
    ull Hp[2][2] = {{0ull, 0ull}, {0ull, 0ull}};

    for (int br = 0; br < 2; br++) {
        // ---- stage W1^T + per-sample vectors ----
        const float* w1t = g_W1T + br * (HH * DD);
#pragma unroll
        for (int i = 0; i < 8; i++) {
            int idx = (tid + i * 512) * 4;
            *(float4*)(sW1T + idx) = *(const float4*)(w1t + idx);
        }
        {
            int smp = tid >> 8, kv = tid & 255;
            size_t gi = (size_t)br * BROFF + (size_t)(s0 + smp) * HH + kv;
            sPb[tid]  = g_p1[gi];
            sAvv[tid] = g_av[gi];
            sBvv[tid] = g_bv[gi];
        }
        __syncthreads();

        float acc[16][4];
#pragma unroll
        for (int i = 0; i < 16; i++)
#pragma unroll
            for (int j = 0; j < 4; j++) acc[i][j] = 0.0f;

        // ---- K slabs: build A (G split), copy B, mma ----
        for (int slab = 0; slab < 4; slab++) {
            // step1: G fp32 into sG (conflict-free transpose staging)
            for (int i2 = 0; i2 < 16; i2++) {
                int idx = tid + i2 * 512;
                int r = idx & 127, kk = idx >> 7;
                int k = slab * 64 + kk;
                sG[r * 66 + kk] = sW1T[k * 64 + (r & 63)] * sPb[(r >> 6) * 256 + k];
            }
            __syncthreads();
            // step2: bf16 hi/lo split into quad-permuted A
            for (int i2 = 0; i2 < 8; i2++) {
                int idx = tid + i2 * 512;
                int pk = idx & 31, r = idx >> 5;
                int kk = 2 * pk;
                float g0, g1;
                unpack2(*(const ull*)(sG + r * 66 + kk), g0, g1);
                __nv_bfloat16 h0 = __float2bfloat16_rn(g0);
                __nv_bfloat16 h1 = __float2bfloat16_rn(g1);
                __nv_bfloat16 l0 = __float2bfloat16_rn(g0 - __bfloat162float(h0));
                __nv_bfloat16 l1 = __float2bfloat16_rn(g1 - __bfloat162float(h1));
                int o = kk & 15;
                int pos = (o < 8) ? ((o >> 1) << 2) : ((((o - 8) >> 1) << 2) + 2);
                int st = r * 80 + (kk & ~15) + pos;
                *(unsigned*)(sAhi + st) =
                    (unsigned)__bfloat16_as_ushort(h0) | ((unsigned)__bfloat16_as_ushort(h1) << 16);
                *(unsigned*)(sAlo + st) =
                    (unsigned)__bfloat16_as_ushort(l0) | ((unsigned)__bfloat16_as_ushort(l1) << 16);
            }
            __syncthreads();
            // B copy (prepped layout -> padded rows)
            for (int i2 = 0; i2 < 8; i2++) {
                int idx = tid + i2 * 512;
                int split = idx >> 11, j = idx & 2047;
                int n = j >> 3, q = j & 7;
                uint4 v = *(const uint4*)((const char*)g_BW2 +
                    (size_t)(br * 2 + split) * 131072 + n * 512 + slab * 128 + q * 16);
                *(uint4*)(smc + OFF_B + split * 40960 + n * 160 + q * 16) = v;
            }
            __syncthreads();
            // mma: 4 k16 steps x 16 n-tiles x 3 split passes
            {
                const unsigned short* aHi = sAhi + (rowtile * 16 + g) * 80 + tq * 4;
                const unsigned short* aLo = sAlo + (rowtile * 16 + g) * 80 + tq * 4;
                const unsigned short* bH  = sBhi + (nhalf * 128 + g) * 80 + tq * 4;
                const unsigned short* bL  = sBlo + (nhalf * 128 + g) * 80 + tq * 4;
                for (int ks = 0; ks < 4; ks++) {
                    int ko = ks * 16;
                    ull Ah0 = *(const ull*)(aHi + ko);
                    ull Ah1 = *(const ull*)(aHi + 640 + ko);
                    ull Al0 = *(const ull*)(aLo + ko);
                    ull Al1 = *(const ull*)(aLo + 640 + ko);
                    unsigned ah0 = (unsigned)Ah0, ah2 = (unsigned)(Ah0 >> 32);
                    unsigned ah1 = (unsigned)Ah1, ah3 = (unsigned)(Ah1 >> 32);
                    unsigned al0 = (unsigned)Al0, al2 = (unsigned)(Al0 >> 32);
                    unsigned al1 = (unsigned)Al1, al3 = (unsigned)(Al1 >> 32);
#pragma unroll
                    for (int nt = 0; nt < 16; nt++) {
                        ull Bh = *(const ull*)(bH + nt * 640 + ko);
                        ull Bl = *(const ull*)(bL + nt * 640 + ko);
                        unsigned bh0 = (unsigned)Bh, bh1 = (unsigned)(Bh >> 32);
                        unsigned bl0 = (unsigned)Bl, bl1 = (unsigned)(Bl >> 32);
                        MMA_BF16(acc[nt], ah0, ah1, ah2, ah3, bh0, bh1);
                        MMA_BF16(acc[nt], ah0, ah1, ah2, ah3, bl0, bl1);
                        MMA_BF16(acc[nt], al0, al1, al2, al3, bh0, bh1);
                    }
                }
            }
            __syncthreads();
        }

        // ---- H2 += F[32:64]*diag(bv)*F^T per sample, 8 chunks of 32 cols ----
#pragma unroll
        for (int jc = 0; jc < 8; jc++) {
            if (nhalf == (jc >> 2)) {
                int smp = rowtile >> 2;
                int r0 = rowtile * 16 + g;
#pragma unroll
                for (int ti = 0; ti < 4; ti++) {
                    int lt = (jc & 3) * 4 + ti;
                    int cb = ti * 8 + 2 * tq;
                    float bc0 = sBvv[smp * 256 + jc * 32 + cb];
                    float bc1 = sBvv[smp * 256 + jc * 32 + cb + 1];
                    sFc [cb * 132 + r0]         = acc[lt][0];
                    sFc [(cb + 1) * 132 + r0]   = acc[lt][1];
                    sFc [cb * 132 + r0 + 8]     = acc[lt][2];
                    sFc [(cb + 1) * 132 + r0 + 8] = acc[lt][3];
                    sFcb[cb * 132 + r0]         = acc[lt][0] * bc0;
                    sFcb[(cb + 1) * 132 + r0]   = acc[lt][1] * bc1;
                    sFcb[cb * 132 + r0 + 8]     = acc[lt][2] * bc0;
                    sFcb[(cb + 1) * 132 + r0 + 8] = acc[lt][3] * bc1;
                }
            }
            __syncthreads();
#pragma unroll 4
            for (int jj = 0; jj < 32; jj++) {
                const float* rbase = sFc + jj * 132 + sel * 64 + 32 + hr;
                ull r0 = *(const ull*)(rbase);
                ull r1 = *(const ull*)(rbase + 2);
                float2 fcv = *(const float2*)(sFcb + jj * 132 + sel * 64 + hc);
                ull c0 = packdup(fcv.x), c1 = packdup(fcv.y);
                ffma2(Hp[0][0], r0, c0); ffma2(Hp[0][1], r0, c1);
                ffma2(Hp[1][0], r1, c0); ffma2(Hp[1][1], r1, c1);
            }
            __syncthreads();
        }

        // ---- H1 += W1 diag(av) W1^T (rows 32:64) per sample ----
        {
            const float* aw = sAvv + sel * 256;
#pragma unroll 4
            for (int k = 0; k < 256; k++) {
                const float* row = sW1T + k * 64;
                float ak = aw[k];
                ull r0 = *(const ull*)(row + 32 + hr);
                ull r1 = *(const ull*)(row + 34 + hr);
                float2 wc = *(const float2*)(row + hc);
                ull c0 = packdup(ak * wc.x), c1 = packdup(ak * wc.y);
                ffma2(Hp[0][0], r0, c0); ffma2(Hp[0][1], r0, c1);
                ffma2(Hp[1][0], r1, c0); ffma2(Hp[1][1], r1, c1);
            }
        }
        __syncthreads();   // before next branch overwrites sW1T / vectors
    }

    // ---- stage H (+2I on A diag), load qdot/jac ----
#pragma unroll
    for (int p = 0; p < 2; p++)
#pragma unroll
        for (int j = 0; j < 2; j++) {
            float f0, f1; unpack2(Hp[p][j], f0, f1);
            int r = hr + 2 * p, c = hc + j;
            if (c == 32 + r)     f0 += 2.0f;
            if (c == 32 + r + 1) f1 += 2.0f;
            sH[sel * 2080 + r * 65 + c]       = f0;
            sH[sel * 2080 + (r + 1) * 65 + c] = f1;
        }
    if (tid < 64) {
        int smp = tid >> 5, i = tid & 31;
        sQ[smp * 32 + i] = x[(size_t)(s0 + smp) * 64 + 32 + i];
        sJ[smp * 32 + i] = g_jl[(size_t)(s0 + smp) * 64 + i];
    }
    __syncthreads();

    // ---- per-sample GE solve: warps 0 (s0) and 8 (s1) ----
    if (wid == 0 || wid == 8) {
        int ss = wid >> 3;
        float* Hm = sH + ss * 2080;
        float* M  = sM + ss * 1056;
        float rhs = sJ[ss * 32 + lane];
        for (int c = 0; c < 32; c++) rhs -= Hm[lane * 65 + c] * sQ[ss * 32 + c];
        for (int j = 0; j < 32; j++) M[lane * 33 + j] = Hm[lane * 65 + 32 + j];
        M[lane * 33 + 32] = rhs;
        __syncwarp();
        for (int k = 0; k < 32; k++) {
            float v = (lane >= k) ? fabsf(M[lane * 33 + k]) : -1.0f;
            int p = lane;
#pragma unroll
            for (int off = 16; off; off >>= 1) {
                float v2 = __shfl_xor_sync(0xffffffffu, v, off);
                int   p2 = __shfl_xor_sync(0xffffffffu, p, off);
                if (v2 > v || (v2 == v && p2 < p)) { v = v2; p = p2; }
            }
            if (p != k) {
                float a = M[k * 33 + lane], b = M[p * 33 + lane];
                M[k * 33 + lane] = b; M[p * 33 + lane] = a;
                if (lane == 0) {
                    float a2 = M[k * 33 + 32], b2 = M[p * 33 + 32];
                    M[k * 33 + 32] = b2; M[p * 33 + 32] = a2;
                }
            }
            __syncwarp();
            if (lane > k) {
                float f = M[lane * 33 + k] / M[k * 33 + k];
                for (int c = k; c <= 32; c++) M[lane * 33 + c] -= f * M[k * 33 + c];
            }
            __syncwarp();
        }
        float accv = 0.0f;
        for (int k = 31; k >= 0; k--) {
            float xk = 0.0f;
            if (lane == k) xk = (M[k * 33 + 32] - accv) / M[k * 33 + k];
            xk = __shfl_sync(0xffffffffu, xk, k);
            if (lane < k) accv += M[lane * 33 + k] * xk;
            if (lane == k) sX[ss * 32 + k] = xk;
        }
    }
    __syncthreads();
    if (tid < 128) {
        int smp = tid >> 6, i = tid & 63;
        out[(size_t)(s0 + smp) * 64 + i] = (i < 32) ? sQ[smp * 32 + i] : sX[smp * 32 + i - 32];
    }
}

// ---------------- host --------------------------------------------------------
extern "C" void kernel_launch(void* const* d_in, const int* in_sizes, int n_in,
                              void* d_out, int out_size) {
    const float* x   = (const float*)d_in[0];
    const float* mW1 = (const float*)d_in[1];
    const float* mb1 = (const float*)d_in[2];
    const float* mW2 = (const float*)d_in[3];
    const float* mb2 = (const float*)d_in[4];
    const float* mW3 = (const float*)d_in[5];
    const float* qW1 = (const float*)d_in[6];
    const float* qb1 = (const float*)d_in[7];
    const float* qW2 = (const float*)d_in[8];
    const float* qb2 = (const float*)d_in[9];
    const float* qW3 = (const float*)d_in[10];
    float* out = (float*)d_out;

    float *h1, *p1, *p2, *u2, *bv, *wv, *av, *jl, *w1t, *w2t;
    cudaGetSymbolAddress((void**)&h1,  g_h1);
    cudaGetSymbolAddress((void**)&p1,  g_p1);
    cudaGetSymbolAddress((void**)&p2,  g_p2);
    cudaGetSymbolAddress((void**)&u2,  g_u2);
    cudaGetSymbolAddress((void**)&bv,  g_bv);
    cudaGetSymbolAddress((void**)&wv,  g_wv);
    cudaGetSymbolAddress((void**)&av,  g_av);
    cudaGetSymbolAddress((void**)&jl,  g_jl);
    cudaGetSymbolAddress((void**)&w1t, g_W1T);
    cudaGetSymbolAddress((void**)&w2t, g_W2T);

    cudaFuncSetAttribute(k_big, cudaFuncAttributeMaxDynamicSharedMemorySize, SMEM_BYTES);

    k_transpose<<<640, 256>>>(mW1, qW1, mW2, qW2);
    k_prepB<<<512, 256>>>(mW2, qW2);

    dim3 g256(64, 4), g64(64, 1);
    for (int br = 0; br < 2; br++) {
        const float* W1 = br ? qW1 : mW1;
        const float* b1 = br ? qb1 : mb1;
        const float* W2 = br ? qW2 : mW2;
        const float* b2 = br ? qb2 : mb2;
        const float* W3 = br ? qW3 : mW3;
        size_t off = (size_t)br * BROFF;

        k_gemm<<<g256, 256>>>(x, W1, 64, 256, br ? EPI_L1_Q : EPI_L1_SP,
                              b1, nullptr, nullptr, nullptr,
                              h1 + off, p1 + off, p2 + off);
        k_gemm<<<g256, 256>>>(h1 + off, W2, 256, 256, br ? EPI_L2_Q : EPI_L2_SP,
                              b2, W3, nullptr, nullptr,
                              u2 + off, bv + off, nullptr);
        k_gemm<<<g256, 256>>>(u2 + off, w2t + (size_t)br * 65536, 256, 256, EPI_V1,
                              nullptr, nullptr, p1 + off, p2 + off,
                              wv + off, av + off, nullptr);
        k_gemm<<<g64, 256>>>(wv + off, w1t + (size_t)br * 16384, 256, 64,
                             br ? EPI_G_ADD : EPI_G_ST,
                             nullptr, nullptr, nullptr, nullptr,
                             jl, nullptr, nullptr);
    }

    k_big<<<BSZ / 2, 512, SMEM_BYTES>>>(x, out);
}

// round 15
// speedup vs baseline: 2.2238x; 1.0929x over previous
#include <cuda_runtime.h>
#include <cuda_bf16.h>
#include <math.h>

#define BSZ 4096
#define DD  64
#define HH  256
#define BROFF (BSZ * HH)

typedef unsigned long long ull;

// ---------------- scratch (device globals) ----------------------------------
__device__ float g_h1[2 * BSZ * HH];
__device__ float g_p1[2 * BSZ * HH];
__device__ float g_p2[2 * BSZ * HH];
__device__ float g_u2[2 * BSZ * HH];
__device__ float g_bv[2 * BSZ * HH];
__device__ float g_wv[2 * BSZ * HH];
__device__ float g_av[2 * BSZ * HH];
__device__ float g_jl[BSZ * DD];
__device__ float g_W1T[2 * HH * DD];            // [k][r] per branch
__device__ float g_W2T[2 * HH * HH];            // [j][i] per branch
// W2^T bf16 hi/lo, [br][split][n][k], k quad-permuted per 16-group for LDS.64 frags
__device__ unsigned short g_BW2[2 * 2 * 65536];

// ---------------- packed f32x2 helpers ---------------------------------------
__device__ __forceinline__ void ffma2(ull& acc, ull a, ull b) {
    asm("fma.rn.f32x2 %0, %1, %2, %0;" : "+l"(acc) : "l"(a), "l"(b));
}
__device__ __forceinline__ ull packdup(float v) {
    ull r; unsigned u = __float_as_uint(v);
    asm("mov.b64 %0, {%1, %1};" : "=l"(r) : "r"(u));
    return r;
}
__device__ __forceinline__ void unpack2(ull v, float& lo, float& hi) {
    unsigned a, b;
    asm("mov.b64 {%0, %1}, %2;" : "=r"(a), "=r"(b) : "l"(v));
    lo = __uint_as_float(a); hi = __uint_as_float(b);
}

// ---------------- warp mma (sm_80 baseline; no arch 'a' feature) -------------
#define MMA_BF16(d, a0, a1, a2, a3, b0, b1) \
    asm volatile("mma.sync.aligned.m16n8k16.row.col.f32.bf16.bf16.f32 " \
        "{%0,%1,%2,%3}, {%4,%5,%6,%7}, {%8,%9}, {%0,%1,%2,%3};" \
        : "+f"((d)[0]), "+f"((d)[1]), "+f"((d)[2]), "+f"((d)[3]) \
        : "r"(a0), "r"(a1), "r"(a2), "r"(a3), "r"(b0), "r"(b1))

// ---------------- activations ------------------------------------------------
__device__ __forceinline__ void act_sp(float z, float& h, float& d1, float& d2) {
    float s = 1.0f / (1.0f + expf(-z));
    h  = fmaxf(z, 0.0f) + log1pf(expf(-fabsf(z)));
    d1 = s;
    d2 = s * (1.0f - s);
}
__device__ __forceinline__ void act_q(float z, float& h, float& d1, float& d2) {
    float t = tanhf(0.5f * z);
    float c = 1.0f - t * t;
    h  = z * t;
    d1 = t + 0.5f * z * c;
    d2 = c * (1.0f - 0.5f * z * t);
}

// ---------------- prep: transposes -------------------------------------------
__global__ void k_transpose(const float* __restrict__ W1m, const float* __restrict__ W1q,
                            const float* __restrict__ W2m, const float* __restrict__ W2q) {
    int tid = blockIdx.x * blockDim.x + threadIdx.x;
    if (tid < 16384) {
        int r = tid / 256, k = tid % 256;
        g_W1T[k * 64 + r] = W1m[tid];
    } else if (tid < 32768) {
        int t = tid - 16384; int r = t / 256, k = t % 256;
        g_W1T[16384 + k * 64 + r] = W1q[t];
    } else if (tid < 98304) {
        int t = tid - 32768; int i = t / 256, j = t % 256;
        g_W2T[j * 256 + i] = W2m[t];
    } else if (tid < 163840) {
        int t = tid - 98304; int i = t / 256, j = t % 256;
        g_W2T[65536 + j * 256 + i] = W2q[t];
    }
}

// ---------------- prep: W2^T bf16 hi with k-quad permutation ------------------
// storage quad t of each 16-k group holds logical k {2t, 2t+1, 2t+8, 2t+9}
__global__ void k_prepB(const float* __restrict__ W2m, const float* __restrict__ W2q) {
    int t = blockIdx.x * blockDim.x + threadIdx.x;
    if (t >= 131072) return;
    int br = t >> 16;
    int e  = t & 65535;
    int k = e >> 8, n = e & 255;
    float v = (br ? W2q : W2m)[k * 256 + n];
    __nv_bfloat16 hb = __float2bfloat16_rn(v);
    int o = k & 15;
    int pos = (o < 8) ? (((o >> 1) << 2) | (o & 1))
                      : ((((o - 8) >> 1) << 2) + 2 + (o & 1));
    int kk = (k & ~15) + pos;
    g_BW2[((size_t)(br * 2 + 0) * 256 + n) * 256 + kk] = __bfloat16_as_ushort(hb);
}

// ---------------- small GEMM with fused epilogues -----------------------------
#define EPI_L1_SP 0
#define EPI_L1_Q  1
#define EPI_L2_SP 2
#define EPI_L2_Q  3
#define EPI_V1    4
#define EPI_G_ST  5
#define EPI_G_ADD 6

__global__ __launch_bounds__(256)
void k_gemm(const float* __restrict__ A, const float* __restrict__ Bm,
            int K, int N, int epi,
            const float* __restrict__ bias, const float* __restrict__ w3,
            const float* __restrict__ e1, const float* __restrict__ e2,
            float* __restrict__ o1, float* __restrict__ o2, float* __restrict__ o3) {
    __shared__ float sA[16][65];
    __shared__ float sB[16][64];
    int tid = threadIdx.x;
    int bm = blockIdx.x * 64, bn = blockIdx.y * 64;
    int ty = tid >> 4, tx = tid & 15;
    int ar = tid >> 2, akq = (tid & 3) * 4;
    int bk = tid >> 4, bnq = (tid & 15) * 4;
    float acc[4][4] = {};
    for (int k0 = 0; k0 < K; k0 += 16) {
        float4 av = *(const float4*)(A + (size_t)(bm + ar) * K + k0 + akq);
        sA[akq + 0][ar] = av.x; sA[akq + 1][ar] = av.y;
        sA[akq + 2][ar] = av.z; sA[akq + 3][ar] = av.w;
        *(float4*)(&sB[bk][bnq]) = *(const float4*)(Bm + (size_t)(k0 + bk) * N + bn + bnq);
        __syncthreads();
#pragma unroll
        for (int kk = 0; kk < 16; kk++) {
            float a[4], b[4];
#pragma unroll
            for (int i = 0; i < 4; i++) a[i] = sA[kk][ty * 4 + i];
#pragma unroll
            for (int j = 0; j < 4; j++) b[j] = sB[kk][tx * 4 + j];
#pragma unroll
            for (int i = 0; i < 4; i++)
#pragma unroll
                for (int j = 0; j < 4; j++) acc[i][j] += a[i] * b[j];
        }
        __syncthreads();
    }
#pragma unroll
    for (int i = 0; i < 4; i++) {
        int s = bm + ty * 4 + i;
#pragma unroll
        for (int j = 0; j < 4; j++) {
            int c = bn + tx * 4 + j;
            float v = acc[i][j];
            size_t idx = (size_t)s * N + c;
            if (epi == EPI_L1_SP) {
                float h, d1, d2; act_sp(v + bias[c], h, d1, d2);
                o1[idx] = h; o2[idx] = d1; o3[idx] = d2;
            } else if (epi == EPI_L1_Q) {
                float h, d1, d2; act_q(v + bias[c], h, d1, d2);
                o1[idx] = h; o2[idx] = d1; o3[idx] = d2;
            } else if (epi == EPI_L2_SP) {
                float h, d1, d2; act_sp(v + bias[c], h, d1, d2);
                float w = w3[c]; o1[idx] = w * d1; o2[idx] = w * d2;
            } else if (epi == EPI_L2_Q) {
                float h, d1, d2; act_q(v + bias[c], h, d1, d2);
                float w = w3[c]; o1[idx] = w * d1; o2[idx] = w * d2;
            } else if (epi == EPI_V1) {
                o1[idx] = e1[idx] * v; o2[idx] = e2[idx] * v;
            } else if (epi == EPI_G_ST) {
                o1[idx] = v;
            } else {
                o1[idx] += v;
            }
        }
    }
}

// ---------------- fused mma.sync Hessian + solve kernel -----------------------
// One CTA = one sample pair (M = 128 F rows), 512 threads / 16 warps.
// warp w: rowtile = w&7 (rows rowtile*16..+15), nhalf = w>>3 (cols nhalf*128..+127)
// 2-pass split: F = (Ghi + Glo) @ hi(W2); residual = G @ lo(W2) ~ 2^-9 rel.
// smem byte offsets:
#define OFF_W1T 0        // 65536  fp32 W1^T [k][r]
#define OFF_A   65536    // 40960  A slab: 128 rows x 80 k-ushort; hi +0, lo +20480
#define OFF_B   106496   // 40960  B slab (hi only): 256 n x 80 k-ushort
                          // aliases on OFF_B region (phase-disjoint):
#define OFF_G   106496   //   33792  fp32 G scratch 128 x 66
#define OFF_FC  106496   //   16896  F chunk  [j][row] 32 x 132 fp32
#define OFF_FCB 123392   //   16896  F*b chunk
#define OFF_M   140288   //   8448   solve matrices 2 x 32 x 33
#define OFF_H   188416   // 16640  sH 2 x 32 x 65
#define OFF_P   205056   // 2048
#define OFF_AV  207104   // 2048
#define OFF_BV  209152   // 2048
#define OFF_Q   211200   // 256
#define OFF_J   211456   // 256
#define OFF_X   211712   // 256
#define SMEM_BYTES 211968

__global__ __launch_bounds__(512, 1)
void k_big(const float* __restrict__ x, float* __restrict__ out) {
    extern __shared__ char smc[];
    float* sW1T = (float*)(smc + OFF_W1T);
    unsigned short* sAhi = (unsigned short*)(smc + OFF_A);
    unsigned short* sAlo = sAhi + 10240;
    unsigned short* sBhi = (unsigned short*)(smc + OFF_B);
    float* sG   = (float*)(smc + OFF_G);
    float* sFc  = (float*)(smc + OFF_FC);
    float* sFcb = (float*)(smc + OFF_FCB);
    float* sM   = (float*)(smc + OFF_M);
    float* sH   = (float*)(smc + OFF_H);
    float* sPb  = (float*)(smc + OFF_P);
    float* sAvv = (float*)(smc + OFF_AV);
    float* sBvv = (float*)(smc + OFF_BV);
    float* sQ   = (float*)(smc + OFF_Q);
    float* sJ   = (float*)(smc + OFF_J);
    float* sX   = (float*)(smc + OFF_X);

    int tid  = threadIdx.x;
    int lane = tid & 31;
    int wid  = tid >> 5;
    int g    = lane >> 2;          // mma group
    int tq   = lane & 3;           // mma thread-in-group
    int rowtile = wid & 7;
    int nhalf   = wid >> 3;
    int s0  = blockIdx.x * 2;

    // H mapping (per 256-thread half = one sample)
    int sel = tid >> 8;
    int hr  = ((tid >> 5) & 7) * 4;
    int hc  = (tid & 31) * 2;
    ull Hp[2][2] = {{0ull, 0ull}, {0ull, 0ull}};

    for (int br = 0; br < 2; br++) {
        // ---- stage W1^T + per-sample vectors ----
        const float* w1t = g_W1T + br * (HH * DD);
#pragma unroll
        for (int i = 0; i < 8; i++) {
            int idx = (tid + i * 512) * 4;
            *(float4*)(sW1T + idx) = *(const float4*)(w1t + idx);
        }
        {
            int smp = tid >> 8, kv = tid & 255;
            size_t gi = (size_t)br * BROFF + (size_t)(s0 + smp) * HH + kv;
            sPb[tid]  = g_p1[gi];
            sAvv[tid] = g_av[gi];
            sBvv[tid] = g_bv[gi];
        }
        __syncthreads();

        float acc[16][4];
#pragma unroll
        for (int i = 0; i < 16; i++)
#pragma unroll
            for (int j = 0; j < 4; j++) acc[i][j] = 0.0f;

        // ---- K slabs: build A (G split), copy B (hi only), mma ----
        for (int slab = 0; slab < 4; slab++) {
            // step1: G fp32 into sG (conflict-free transpose staging)
            for (int i2 = 0; i2 < 16; i2++) {
                int idx = tid + i2 * 512;
                int r = idx & 127, kk = idx >> 7;
                int k = slab * 64 + kk;
                sG[r * 66 + kk] = sW1T[k * 64 + (r & 63)] * sPb[(r >> 6) * 256 + k];
            }
            __syncthreads();
            // step2: bf16 hi/lo split into quad-permuted A
            for (int i2 = 0; i2 < 8; i2++) {
                int idx = tid + i2 * 512;
                int pk = idx & 31, r = idx >> 5;
                int kk = 2 * pk;
                float g0, g1;
                unpack2(*(const ull*)(sG + r * 66 + kk), g0, g1);
                __nv_bfloat16 h0 = __float2bfloat16_rn(g0);
                __nv_bfloat16 h1 = __float2bfloat16_rn(g1);
                __nv_bfloat16 l0 = __float2bfloat16_rn(g0 - __bfloat162float(h0));
                __nv_bfloat16 l1 = __float2bfloat16_rn(g1 - __bfloat162float(h1));
                int o = kk & 15;
                int pos = (o < 8) ? ((o >> 1) << 2) : ((((o - 8) >> 1) << 2) + 2);
                int st = r * 80 + (kk & ~15) + pos;
                *(unsigned*)(sAhi + st) =
                    (unsigned)__bfloat16_as_ushort(h0) | ((unsigned)__bfloat16_as_ushort(h1) << 16);
                *(unsigned*)(sAlo + st) =
                    (unsigned)__bfloat16_as_ushort(l0) | ((unsigned)__bfloat16_as_ushort(l1) << 16);
            }
            __syncthreads();
            // B copy (hi split only: 256 n-rows x 128 data bytes, 160B stride)
            for (int i2 = 0; i2 < 4; i2++) {
                int idx = tid + i2 * 512;
                int n = idx >> 3, q = idx & 7;
                uint4 v = *(const uint4*)((const char*)g_BW2 +
                    (size_t)(br * 2) * 131072 + n * 512 + slab * 128 + q * 16);
                *(uint4*)(smc + OFF_B + n * 160 + q * 16) = v;
            }
            __syncthreads();
            // mma: 4 k16 steps x 16 n-tiles x 2 split passes (Ahi*Bh + Alo*Bh)
            {
                const unsigned short* aHi = sAhi + (rowtile * 16 + g) * 80 + tq * 4;
                const unsigned short* aLo = sAlo + (rowtile * 16 + g) * 80 + tq * 4;
                const unsigned short* bH  = sBhi + (nhalf * 128 + g) * 80 + tq * 4;
                for (int ks = 0; ks < 4; ks++) {
                    int ko = ks * 16;
                    ull Ah0 = *(const ull*)(aHi + ko);
                    ull Ah1 = *(const ull*)(aHi + 640 + ko);
                    ull Al0 = *(const ull*)(aLo + ko);
                    ull Al1 = *(const ull*)(aLo + 640 + ko);
                    unsigned ah0 = (unsigned)Ah0, ah2 = (unsigned)(Ah0 >> 32);
                    unsigned ah1 = (unsigned)Ah1, ah3 = (unsigned)(Ah1 >> 32);
                    unsigned al0 = (unsigned)Al0, al2 = (unsigned)(Al0 >> 32);
                    unsigned al1 = (unsigned)Al1, al3 = (unsigned)(Al1 >> 32);
#pragma unroll
                    for (int nt = 0; nt < 16; nt++) {
                        ull Bh = *(const ull*)(bH + nt * 640 + ko);
                        unsigned bh0 = (unsigned)Bh, bh1 = (unsigned)(Bh >> 32);
                        MMA_BF16(acc[nt], ah0, ah1, ah2, ah3, bh0, bh1);
                        MMA_BF16(acc[nt], al0, al1, al2, al3, bh0, bh1);
                    }
                }
            }
            __syncthreads();
        }

        // ---- H2 += F[32:64]*diag(bv)*F^T per sample, 8 chunks of 32 cols ----
#pragma unroll
        for (int jc = 0; jc < 8; jc++) {
            if (nhalf == (jc >> 2)) {
                int smp = rowtile >> 2;
                int r0 = rowtile * 16 + g;
#pragma unroll
                for (int ti = 0; ti < 4; ti++) {
                    int lt = (jc & 3) * 4 + ti;
                    int cb = ti * 8 + 2 * tq;
                    float bc0 = sBvv[smp * 256 + jc * 32 + cb];
                    float bc1 = sBvv[smp * 256 + jc * 32 + cb + 1];
                    sFc [cb * 132 + r0]         = acc[lt][0];
                    sFc [(cb + 1) * 132 + r0]   = acc[lt][1];
                    sFc [cb * 132 + r0 + 8]     = acc[lt][2];
                    sFc [(cb + 1) * 132 + r0 + 8] = acc[lt][3];
                    sFcb[cb * 132 + r0]         = acc[lt][0] * bc0;
                    sFcb[(cb + 1) * 132 + r0]   = acc[lt][1] * bc1;
                    sFcb[cb * 132 + r0 + 8]     = acc[lt][2] * bc0;
                    sFcb[(cb + 1) * 132 + r0 + 8] = acc[lt][3] * bc1;
                }
            }
            __syncthreads();
#pragma unroll 4
            for (int jj = 0; jj < 32; jj++) {
                const float* rbase = sFc + jj * 132 + sel * 64 + 32 + hr;
                ull r0 = *(const ull*)(rbase);
                ull r1 = *(const ull*)(rbase + 2);
                float2 fcv = *(const float2*)(sFcb + jj * 132 + sel * 64 + hc);
                ull c0 = packdup(fcv.x), c1 = packdup(fcv.y);
                ffma2(Hp[0][0], r0, c0); ffma2(Hp[0][1], r0, c1);
                ffma2(Hp[1][0], r1, c0); ffma2(Hp[1][1], r1, c1);
            }
            __syncthreads();
        }

        // ---- H1 += W1 diag(av) W1^T (rows 32:64) per sample ----
        {
            const float* aw = sAvv + sel * 256;
#pragma unroll 4
            for (int k = 0; k < 256; k++) {
                const float* row = sW1T + k * 64;
                float ak = aw[k];
                ull r0 = *(const ull*)(row + 32 + hr);
                ull r1 = *(const ull*)(row + 34 + hr);
                float2 wc = *(const float2*)(row + hc);
                ull c0 = packdup(ak * wc.x), c1 = packdup(ak * wc.y);
                ffma2(Hp[0][0], r0, c0); ffma2(Hp[0][1], r0, c1);
                ffma2(Hp[1][0], r1, c0); ffma2(Hp[1][1], r1, c1);
            }
        }
        __syncthreads();   // before next branch overwrites sW1T / vectors
    }

    // ---- stage H (+2I on A diag), load qdot/jac ----
#pragma unroll
    for (int p = 0; p < 2; p++)
#pragma unroll
        for (int j = 0; j < 2; j++) {
            float f0, f1; unpack2(Hp[p][j], f0, f1);
            int r = hr + 2 * p, c = hc + j;
            if (c == 32 + r)     f0 += 2.0f;
            if (c == 32 + r + 1) f1 += 2.0f;
            sH[sel * 2080 + r * 65 + c]       = f0;
            sH[sel * 2080 + (r + 1) * 65 + c] = f1;
        }
    if (tid < 64) {
        int smp = tid >> 5, i = tid & 31;
        sQ[smp * 32 + i] = x[(size_t)(s0 + smp) * 64 + 32 + i];
        sJ[smp * 32 + i] = g_jl[(size_t)(s0 + smp) * 64 + i];
    }
    __syncthreads();

    // ---- per-sample GE solve: warps 0 (s0) and 8 (s1) ----
    if (wid == 0 || wid == 8) {
        int ss = wid >> 3;
        float* Hm = sH + ss * 2080;
        float* M  = sM + ss * 1056;
        float rhs = sJ[ss * 32 + lane];
        for (int c = 0; c < 32; c++) rhs -= Hm[lane * 65 + c] * sQ[ss * 32 + c];
        for (int j = 0; j < 32; j++) M[lane * 33 + j] = Hm[lane * 65 + 32 + j];
        M[lane * 33 + 32] = rhs;
        __syncwarp();
        for (int k = 0; k < 32; k++) {
            float v = (lane >= k) ? fabsf(M[lane * 33 + k]) : -1.0f;
            int p = lane;
#pragma unroll
            for (int off = 16; off; off >>= 1) {
                float v2 = __shfl_xor_sync(0xffffffffu, v, off);
                int   p2 = __shfl_xor_sync(0xffffffffu, p, off);
                if (v2 > v || (v2 == v && p2 < p)) { v = v2; p = p2; }
            }
            if (p != k) {
                float a = M[k * 33 + lane], b = M[p * 33 + lane];
                M[k * 33 + lane] = b; M[p * 33 + lane] = a;
                if (lane == 0) {
                    float a2 = M[k * 33 + 32], b2 = M[p * 33 + 32];
                    M[k * 33 + 32] = b2; M[p * 33 + 32] = a2;
                }
            }
            __syncwarp();
            if (lane > k) {
                float f = M[lane * 33 + k] / M[k * 33 + k];
                for (int c = k; c <= 32; c++) M[lane * 33 + c] -= f * M[k * 33 + c];
            }
            __syncwarp();
        }
        float accv = 0.0f;
        for (int k = 31; k >= 0; k--) {
            float xk = 0.0f;
            if (lane == k) xk = (M[k * 33 + 32] - accv) / M[k * 33 + k];
            xk = __shfl_sync(0xffffffffu, xk, k);
            if (lane < k) accv += M[lane * 33 + k] * xk;
            if (lane == k) sX[ss * 32 + k] = xk;
        }
    }
    __syncthreads();
    if (tid < 128) {
        int smp = tid >> 6, i = tid & 63;
        out[(size_t)(s0 + smp) * 64 + i] = (i < 32) ? sQ[smp * 32 + i] : sX[smp * 32 + i - 32];
    }
}

// ---------------- host --------------------------------------------------------
extern "C" void kernel_launch(void* const* d_in, const int* in_sizes, int n_in,
                              void* d_out, int out_size) {
    const float* x   = (const float*)d_in[0];
    const float* mW1 = (const float*)d_in[1];
    const float* mb1 = (const float*)d_in[2];
    const float* mW2 = (const float*)d_in[3];
    const float* mb2 = (const float*)d_in[4];
    const float* mW3 = (const float*)d_in[5];
    const float* qW1 = (const float*)d_in[6];
    const float* qb1 = (const float*)d_in[7];
    const float* qW2 = (const float*)d_in[8];
    const float* qb2 = (const float*)d_in[9];
    const float* qW3 = (const float*)d_in[10];
    float* out = (float*)d_out;

    float *h1, *p1, *p2, *u2, *bv, *wv, *av, *jl, *w1t, *w2t;
    cudaGetSymbolAddress((void**)&h1,  g_h1);
    cudaGetSymbolAddress((void**)&p1,  g_p1);
    cudaGetSymbolAddress((void**)&p2,  g_p2);
    cudaGetSymbolAddress((void**)&u2,  g_u2);
    cudaGetSymbolAddress((void**)&bv,  g_bv);
    cudaGetSymbolAddress((void**)&wv,  g_wv);
    cudaGetSymbolAddress((void**)&av,  g_av);
    cudaGetSymbolAddress((void**)&jl,  g_jl);
    cudaGetSymbolAddress((void**)&w1t, g_W1T);
    cudaGetSymbolAddress((void**)&w2t, g_W2T);

    cudaFuncSetAttribute(k_big, cudaFuncAttributeMaxDynamicSharedMemorySize, SMEM_BYTES);

    k_transpose<<<640, 256>>>(mW1, qW1, mW2, qW2);
    k_prepB<<<512, 256>>>(mW2, qW2);

    dim3 g256(64, 4), g64(64, 1);
    for (int br = 0; br < 2; br++) {
        const float* W1 = br ? qW1 : mW1;
        const float* b1 = br ? qb1 : mb1;
        const float* W2 = br ? qW2 : mW2;
        const float* b2 = br ? qb2 : mb2;
        const float* W3 = br ? qW3 : mW3;
        size_t off = (size_t)br * BROFF;

        k_gemm<<<g256, 256>>>(x, W1, 64, 256, br ? EPI_L1_Q : EPI_L1_SP,
                              b1, nullptr, nullptr, nullptr,
                              h1 + off, p1 + off, p2 + off);
        k_gemm<<<g256, 256>>>(h1 + off, W2, 256, 256, br ? EPI_L2_Q : EPI_L2_SP,
                              b2, W3, nullptr, nullptr,
                              u2 + off, bv + off, nullptr);
        k_gemm<<<g256, 256>>>(u2 + off, w2t + (size_t)br * 65536, 256, 256, EPI_V1,
                              nullptr, nullptr, p1 + off, p2 + off,
                              wv + off, av + off, nullptr);
        k_gemm<<<g64, 256>>>(wv + off, w1t + (size_t)br * 16384, 256, 64,
                             br ? EPI_G_ADD : EPI_G_ST,
                             nullptr, nullptr, nullptr, nullptr,
                             jl, nullptr, nullptr);
    }

    k_big<<<BSZ / 2, 512, SMEM_BYTES>>>(x, out);
}

// round 16
// speedup vs baseline: 2.6198x; 1.1780x over previous
#include <cuda_runtime.h>
#include <cuda_bf16.h>
#include <math.h>

#define BSZ 4096
#define DD  64
#define HH  256
#define BROFF (BSZ * HH)

typedef unsigned long long ull;

// ---------------- scratch (device globals) ----------------------------------
__device__ float g_h1[2 * BSZ * HH];
__device__ float g_p1[2 * BSZ * HH];
__device__ float g_p2[2 * BSZ * HH];
__device__ float g_u2[2 * BSZ * HH];
__device__ float g_bv[2 * BSZ * HH];
__device__ float g_wv[2 * BSZ * HH];
__device__ float g_av[2 * BSZ * HH];
__device__ float g_jl[BSZ * DD];
__device__ float g_W1T[2 * HH * DD];            // [k][r] per branch
__device__ float g_W2T[2 * HH * HH];            // [j][i] per branch
// W2^T bf16 hi, [br][split][n][k], k quad-permuted per 16-group for LDS.64 frags
__device__ unsigned short g_BW2[2 * 2 * 65536];

// ---------------- packed f32x2 helpers ---------------------------------------
__device__ __forceinline__ void ffma2(ull& acc, ull a, ull b) {
    asm("fma.rn.f32x2 %0, %1, %2, %0;" : "+l"(acc) : "l"(a), "l"(b));
}
__device__ __forceinline__ ull packdup(float v) {
    ull r; unsigned u = __float_as_uint(v);
    asm("mov.b64 %0, {%1, %1};" : "=l"(r) : "r"(u));
    return r;
}
__device__ __forceinline__ void unpack2(ull v, float& lo, float& hi) {
    unsigned a, b;
    asm("mov.b64 {%0, %1}, %2;" : "=r"(a), "=r"(b) : "l"(v));
    lo = __uint_as_float(a); hi = __uint_as_float(b);
}
// pack 2 floats -> bf16x2 (lo in lower ushort)
__device__ __forceinline__ unsigned bf16pack(float lo, float hi) {
    unsigned r;
    asm("cvt.rn.bf16x2.f32 %0, %1, %2;" : "=r"(r) : "f"(hi), "f"(lo));
    return r;
}

// ---------------- warp mma (sm_80 baseline; no arch 'a' feature) -------------
#define MMA_BF16(d, a0, a1, a2, a3, b0, b1) \
    asm volatile("mma.sync.aligned.m16n8k16.row.col.f32.bf16.bf16.f32 " \
        "{%0,%1,%2,%3}, {%4,%5,%6,%7}, {%8,%9}, {%0,%1,%2,%3};" \
        : "+f"((d)[0]), "+f"((d)[1]), "+f"((d)[2]), "+f"((d)[3]) \
        : "r"(a0), "r"(a1), "r"(a2), "r"(a3), "r"(b0), "r"(b1))

// ---------------- activations ------------------------------------------------
__device__ __forceinline__ void act_sp(float z, float& h, float& d1, float& d2) {
    float s = 1.0f / (1.0f + expf(-z));
    h  = fmaxf(z, 0.0f) + log1pf(expf(-fabsf(z)));
    d1 = s;
    d2 = s * (1.0f - s);
}
__device__ __forceinline__ void act_q(float z, float& h, float& d1, float& d2) {
    float t = tanhf(0.5f * z);
    float c = 1.0f - t * t;
    h  = z * t;
    d1 = t + 0.5f * z * c;
    d2 = c * (1.0f - 0.5f * z * t);
}

// ---------------- prep: transposes -------------------------------------------
__global__ void k_transpose(const float* __restrict__ W1m, const float* __restrict__ W1q,
                            const float* __restrict__ W2m, const float* __restrict__ W2q) {
    int tid = blockIdx.x * blockDim.x + threadIdx.x;
    if (tid < 16384) {
        int r = tid / 256, k = tid % 256;
        g_W1T[k * 64 + r] = W1m[tid];
    } else if (tid < 32768) {
        int t = tid - 16384; int r = t / 256, k = t % 256;
        g_W1T[16384 + k * 64 + r] = W1q[t];
    } else if (tid < 98304) {
        int t = tid - 32768; int i = t / 256, j = t % 256;
        g_W2T[j * 256 + i] = W2m[t];
    } else if (tid < 163840) {
        int t = tid - 98304; int i = t / 256, j = t % 256;
        g_W2T[65536 + j * 256 + i] = W2q[t];
    }
}

// ---------------- prep: W2^T bf16 hi with k-quad permutation ------------------
// storage quad t of each 16-k group holds logical k {2t, 2t+1, 2t+8, 2t+9}
__global__ void k_prepB(const float* __restrict__ W2m, const float* __restrict__ W2q) {
    int t = blockIdx.x * blockDim.x + threadIdx.x;
    if (t >= 131072) return;
    int br = t >> 16;
    int e  = t & 65535;
    int k = e >> 8, n = e & 255;
    float v = (br ? W2q : W2m)[k * 256 + n];
    __nv_bfloat16 hb = __float2bfloat16_rn(v);
    int o = k & 15;
    int pos = (o < 8) ? (((o >> 1) << 2) | (o & 1))
                      : ((((o - 8) >> 1) << 2) + 2 + (o & 1));
    int kk = (k & ~15) + pos;
    g_BW2[((size_t)(br * 2 + 0) * 256 + n) * 256 + kk] = __bfloat16_as_ushort(hb);
}

// ---------------- small GEMM with fused epilogues -----------------------------
#define EPI_L1_SP 0
#define EPI_L1_Q  1
#define EPI_L2_SP 2
#define EPI_L2_Q  3
#define EPI_V1    4
#define EPI_G_ST  5
#define EPI_G_ADD 6

__global__ __launch_bounds__(256)
void k_gemm(const float* __restrict__ A, const float* __restrict__ Bm,
            int K, int N, int epi,
            const float* __restrict__ bias, const float* __restrict__ w3,
            const float* __restrict__ e1, const float* __restrict__ e2,
            float* __restrict__ o1, float* __restrict__ o2, float* __restrict__ o3) {
    __shared__ float sA[16][65];
    __shared__ float sB[16][64];
    int tid = threadIdx.x;
    int bm = blockIdx.x * 64, bn = blockIdx.y * 64;
    int ty = tid >> 4, tx = tid & 15;
    int ar = tid >> 2, akq = (tid & 3) * 4;
    int bk = tid >> 4, bnq = (tid & 15) * 4;
    float acc[4][4] = {};
    for (int k0 = 0; k0 < K; k0 += 16) {
        float4 av = *(const float4*)(A + (size_t)(bm + ar) * K + k0 + akq);
        sA[akq + 0][ar] = av.x; sA[akq + 1][ar] = av.y;
        sA[akq + 2][ar] = av.z; sA[akq + 3][ar] = av.w;
        *(float4*)(&sB[bk][bnq]) = *(const float4*)(Bm + (size_t)(k0 + bk) * N + bn + bnq);
        __syncthreads();
#pragma unroll
        for (int kk = 0; kk < 16; kk++) {
            float a[4], b[4];
#pragma unroll
            for (int i = 0; i < 4; i++) a[i] = sA[kk][ty * 4 + i];
#pragma unroll
            for (int j = 0; j < 4; j++) b[j] = sB[kk][tx * 4 + j];
#pragma unroll
            for (int i = 0; i < 4; i++)
#pragma unroll
                for (int j = 0; j < 4; j++) acc[i][j] += a[i] * b[j];
        }
        __syncthreads();
    }
#pragma unroll
    for (int i = 0; i < 4; i++) {
        int s = bm + ty * 4 + i;
#pragma unroll
        for (int j = 0; j < 4; j++) {
            int c = bn + tx * 4 + j;
            float v = acc[i][j];
            size_t idx = (size_t)s * N + c;
            if (epi == EPI_L1_SP) {
                float h, d1, d2; act_sp(v + bias[c], h, d1, d2);
                o1[idx] = h; o2[idx] = d1; o3[idx] = d2;
            } else if (epi == EPI_L1_Q) {
                float h, d1, d2; act_q(v + bias[c], h, d1, d2);
                o1[idx] = h; o2[idx] = d1; o3[idx] = d2;
            } else if (epi == EPI_L2_SP) {
                float h, d1, d2; act_sp(v + bias[c], h, d1, d2);
                float w = w3[c]; o1[idx] = w * d1; o2[idx] = w * d2;
            } else if (epi == EPI_L2_Q) {
                float h, d1, d2; act_q(v + bias[c], h, d1, d2);
                float w = w3[c]; o1[idx] = w * d1; o2[idx] = w * d2;
            } else if (epi == EPI_V1) {
                o1[idx] = e1[idx] * v; o2[idx] = e2[idx] * v;
            } else if (epi == EPI_G_ST) {
                o1[idx] = v;
            } else {
                o1[idx] += v;
            }
        }
    }
}

// ---------------- fused mma.sync Hessian + solve kernel -----------------------
// One CTA = one sample pair (M = 128 F rows), 512 threads / 16 warps.
// warp w: rowtile = w&7, nhalf = w>>3.  2-pass split mainloop (Ahi+Alo)*Bhi.
// H2 via mma on bf16 F (stored post-mainloop, aliasing A/B regions).
// smem byte offsets:
#define OFF_W1T 0        // 65536  fp32 W1^T [k][r]
#define OFF_A   65536    // 40960  A slab: 128 rows x 80 k-ushort; hi +0, lo +20480
#define OFF_B   106496   // 40960  B slab (hi only): 256 n x 80 k-ushort
#define OFF_G   106496   //   33792  fp32 G scratch 128 x 66 (aliases B, phase-disjoint)
#define OFF_F   65536    // 67584  F bf16 [128 rows][264 j] (aliases A+B, post-mainloop)
#define OFF_AB  133120   // 33792  Ab bf16 [64 rows][264 j] (aliases M region, phase-disjoint)
#define OFF_M   140288   //   8448   solve matrices 2 x 32 x 33 (solve phase only)
#define OFF_H   188416   // 16640  sH 2 x 32 x 65
#define OFF_P   205056   // 2048
#define OFF_AV  207104   // 2048
#define OFF_BV  209152   // 2048
#define OFF_Q   211200   // 256
#define OFF_J   211456   // 256
#define OFF_X   211712   // 256
#define SMEM_BYTES 211968

__global__ __launch_bounds__(512, 1)
void k_big(const float* __restrict__ x, float* __restrict__ out) {
    extern __shared__ char smc[];
    float* sW1T = (float*)(smc + OFF_W1T);
    unsigned short* sAhi = (unsigned short*)(smc + OFF_A);
    unsigned short* sAlo = sAhi + 10240;
    unsigned short* sBhi = (unsigned short*)(smc + OFF_B);
    unsigned short* sF   = (unsigned short*)(smc + OFF_F);
    unsigned short* sAb  = (unsigned short*)(smc + OFF_AB);
    float* sG   = (float*)(smc + OFF_G);
    float* sM   = (float*)(smc + OFF_M);
    float* sH   = (float*)(smc + OFF_H);
    float* sPb  = (float*)(smc + OFF_P);
    float* sAvv = (float*)(smc + OFF_AV);
    float* sBvv = (float*)(smc + OFF_BV);
    float* sQ   = (float*)(smc + OFF_Q);
    float* sJ   = (float*)(smc + OFF_J);
    float* sX   = (float*)(smc + OFF_X);

    int tid  = threadIdx.x;
    int lane = tid & 31;
    int wid  = tid >> 5;
    int g    = lane >> 2;          // mma group
    int tq   = lane & 3;           // mma thread-in-group
    int rowtile = wid & 7;
    int nhalf   = wid >> 3;
    int s0  = blockIdx.x * 2;

    // H1 scalar mapping (per 256-thread half = one sample)
    int sel = tid >> 8;
    int hr  = ((tid >> 5) & 7) * 4;
    int hc  = (tid & 31) * 2;
    ull Hp[2][2] = {{0ull, 0ull}, {0ull, 0ull}};

    // H2 mma accumulators (persist across branches): warp = (sample, mtile, npair)
    int h2s = wid >> 3, h2m = (wid >> 2) & 1, h2n = wid & 3;
    float d2[2][4];
#pragma unroll
    for (int t = 0; t < 2; t++)
#pragma unroll
        for (int j = 0; j < 4; j++) d2[t][j] = 0.0f;

    // Ab staging ownership (F rows 32:64 per sample = rowtiles 2,3,6,7)
    bool isAb = (rowtile == 2 || rowtile == 3 || rowtile == 6 || rowtile == 7);
    int abS   = rowtile >> 2;                         // sample of this rowtile
    int abRow = abS * 32 + (rowtile & 1) * 16 + g;    // row in Ab (valid when isAb)

    for (int br = 0; br < 2; br++) {
        // ---- stage W1^T + per-sample vectors ----
        const float* w1t = g_W1T + br * (HH * DD);
#pragma unroll
        for (int i = 0; i < 8; i++) {
            int idx = (tid + i * 512) * 4;
            *(float4*)(sW1T + idx) = *(const float4*)(w1t + idx);
        }
        {
            int smp = tid >> 8, kv = tid & 255;
            size_t gi = (size_t)br * BROFF + (size_t)(s0 + smp) * HH + kv;
            sPb[tid]  = g_p1[gi];
            sAvv[tid] = g_av[gi];
            sBvv[tid] = g_bv[gi];
        }
        __syncthreads();

        float acc[16][4];
#pragma unroll
        for (int i = 0; i < 16; i++)
#pragma unroll
            for (int j = 0; j < 4; j++) acc[i][j] = 0.0f;

        // ---- K slabs: prefetch B, build A (G split), store B, mma ----
        for (int slab = 0; slab < 4; slab++) {
            // B prefetch into registers (overlaps with G-build/A-split)
            uint4 bpre[4];
#pragma unroll
            for (int i2 = 0; i2 < 4; i2++) {
                int idx = tid + i2 * 512;
                int n = idx >> 3, q = idx & 7;
                bpre[i2] = *(const uint4*)((const char*)g_BW2 +
                    (size_t)(br * 2) * 131072 + n * 512 + slab * 128 + q * 16);
            }
            // step1: G fp32 into sG (conflict-free transpose staging)
            for (int i2 = 0; i2 < 16; i2++) {
                int idx = tid + i2 * 512;
                int r = idx & 127, kk = idx >> 7;
                int k = slab * 64 + kk;
                sG[r * 66 + kk] = sW1T[k * 64 + (r & 63)] * sPb[(r >> 6) * 256 + k];
            }
            __syncthreads();
            // step2: bf16 hi/lo split into quad-permuted A
            for (int i2 = 0; i2 < 8; i2++) {
                int idx = tid + i2 * 512;
                int pk = idx & 31, r = idx >> 5;
                int kk = 2 * pk;
                float g0, g1;
                unpack2(*(const ull*)(sG + r * 66 + kk), g0, g1);
                __nv_bfloat16 h0 = __float2bfloat16_rn(g0);
                __nv_bfloat16 h1 = __float2bfloat16_rn(g1);
                __nv_bfloat16 l0 = __float2bfloat16_rn(g0 - __bfloat162float(h0));
                __nv_bfloat16 l1 = __float2bfloat16_rn(g1 - __bfloat162float(h1));
                int o = kk & 15;
                int pos = (o < 8) ? ((o >> 1) << 2) : ((((o - 8) >> 1) << 2) + 2);
                int st = r * 80 + (kk & ~15) + pos;
                *(unsigned*)(sAhi + st) =
                    (unsigned)__bfloat16_as_ushort(h0) | ((unsigned)__bfloat16_as_ushort(h1) << 16);
                *(unsigned*)(sAlo + st) =
                    (unsigned)__bfloat16_as_ushort(l0) | ((unsigned)__bfloat16_as_ushort(l1) << 16);
            }
            __syncthreads();
            // B store from prefetched registers
#pragma unroll
            for (int i2 = 0; i2 < 4; i2++) {
                int idx = tid + i2 * 512;
                int n = idx >> 3, q = idx & 7;
                *(uint4*)(smc + OFF_B + n * 160 + q * 16) = bpre[i2];
            }
            __syncthreads();
            // mma: 4 k16 steps x 16 n-tiles x 2 split passes (Ahi*Bh + Alo*Bh)
            {
                const unsigned short* aHi = sAhi + (rowtile * 16 + g) * 80 + tq * 4;
                const unsigned short* aLo = sAlo + (rowtile * 16 + g) * 80 + tq * 4;
                const unsigned short* bH  = sBhi + (nhalf * 128 + g) * 80 + tq * 4;
                for (int ks = 0; ks < 4; ks++) {
                    int ko = ks * 16;
                    ull Ah0 = *(const ull*)(aHi + ko);
                    ull Ah1 = *(const ull*)(aHi + 640 + ko);
                    ull Al0 = *(const ull*)(aLo + ko);
                    ull Al1 = *(const ull*)(aLo + 640 + ko);
                    unsigned ah0 = (unsigned)Ah0, ah2 = (unsigned)(Ah0 >> 32);
                    unsigned ah1 = (unsigned)Ah1, ah3 = (unsigned)(Ah1 >> 32);
                    unsigned al0 = (unsigned)Al0, al2 = (unsigned)(Al0 >> 32);
                    unsigned al1 = (unsigned)Al1, al3 = (unsigned)(Al1 >> 32);
#pragma unroll
                    for (int nt = 0; nt < 16; nt++) {
                        ull Bh = *(const ull*)(bH + nt * 640 + ko);
                        unsigned bh0 = (unsigned)Bh, bh1 = (unsigned)(Bh >> 32);
                        MMA_BF16(acc[nt], ah0, ah1, ah2, ah3, bh0, bh1);
                        MMA_BF16(acc[nt], al0, al1, al2, al3, bh0, bh1);
                    }
                }
            }
            __syncthreads();
        }

        // ---- store F (all warps) + Ab = F*diag(bv) rows 32:64 (8 warps) ----
        {
            int r0 = rowtile * 16 + g;
#pragma unroll
            for (int nt = 0; nt < 16; nt++) {
                int j0 = nhalf * 128 + nt * 8 + 2 * tq;
                int base = (j0 & ~15) + tq * 4 + (nt & 1) * 2;
                *(unsigned*)(sF + r0 * 264 + base)       = bf16pack(acc[nt][0], acc[nt][1]);
                *(unsigned*)(sF + (r0 + 8) * 264 + base) = bf16pack(acc[nt][2], acc[nt][3]);
                if (isAb) {
                    float b0 = sBvv[abS * 256 + j0];
                    float b1 = sBvv[abS * 256 + j0 + 1];
                    *(unsigned*)(sAb + abRow * 264 + base) =
                        bf16pack(acc[nt][0] * b0, acc[nt][1] * b1);
                    *(unsigned*)(sAb + (abRow + 8) * 264 + base) =
                        bf16pack(acc[nt][2] * b0, acc[nt][3] * b1);
                }
            }
        }
        __syncthreads();

        // ---- H2 mma: D2[s] += Ab[s] @ F[s]^T  (M=32, N=64, K=256 per sample) ----
        {
            const unsigned short* Ap = sAb + (h2s * 32 + h2m * 16 + g) * 264 + tq * 4;
            const unsigned short* B0 = sF + (h2s * 64 + (h2n * 2 + 0) * 8 + g) * 264 + tq * 4;
            const unsigned short* B1 = B0 + 8 * 264;
#pragma unroll 4
            for (int kg = 0; kg < 16; kg++) {
                int ko = kg * 16;
                ull A0 = *(const ull*)(Ap + ko);
                ull A1 = *(const ull*)(Ap + 8 * 264 + ko);
                unsigned a0 = (unsigned)A0, a2 = (unsigned)(A0 >> 32);
                unsigned a1 = (unsigned)A1, a3 = (unsigned)(A1 >> 32);
                ull Bq0 = *(const ull*)(B0 + ko);
                ull Bq1 = *(const ull*)(B1 + ko);
                MMA_BF16(d2[0], a0, a1, a2, a3, (unsigned)Bq0, (unsigned)(Bq0 >> 32));
                MMA_BF16(d2[1], a0, a1, a2, a3, (unsigned)Bq1, (unsigned)(Bq1 >> 32));
            }
        }

        // ---- H1 += W1 diag(av) W1^T (rows 32:64) per sample, scalar ----
        {
            const float* aw = sAvv + sel * 256;
#pragma unroll 4
            for (int k = 0; k < 256; k++) {
                const float* row = sW1T + k * 64;
                float ak = aw[k];
                ull r0 = *(const ull*)(row + 32 + hr);
                ull r1 = *(const ull*)(row + 34 + hr);
                float2 wc = *(const float2*)(row + hc);
                ull c0 = packdup(ak * wc.x), c1 = packdup(ak * wc.y);
                ffma2(Hp[0][0], r0, c0); ffma2(Hp[0][1], r0, c1);
                ffma2(Hp[1][0], r1, c0); ffma2(Hp[1][1], r1, c1);
            }
        }
        __syncthreads();   // F reads done; next branch may overwrite staging
    }

    // ---- epilogue: D2 -> sH (fragment mapping), then H1 += (+2I) ----
#pragma unroll
    for (int t = 0; t < 2; t++) {
        int n0 = (h2n * 2 + t) * 8 + 2 * tq;
        float* Hrow = sH + h2s * 2080 + (h2m * 16 + g) * 65;
        Hrow[n0]            = d2[t][0];
        Hrow[n0 + 1]        = d2[t][1];
        Hrow[8 * 65 + n0]     = d2[t][2];
        Hrow[8 * 65 + n0 + 1] = d2[t][3];
    }
    __syncthreads();
#pragma unroll
    for (int p = 0; p < 2; p++)
#pragma unroll
        for (int j = 0; j < 2; j++) {
            float f0, f1; unpack2(Hp[p][j], f0, f1);
            int r = hr + 2 * p, c = hc + j;
            if (c == 32 + r)     f0 += 2.0f;
            if (c == 32 + r + 1) f1 += 2.0f;
            sH[sel * 2080 + r * 65 + c]       += f0;
            sH[sel * 2080 + (r + 1) * 65 + c] += f1;
        }
    if (tid < 64) {
        int smp = tid >> 5, i = tid & 31;
        sQ[smp * 32 + i] = x[(size_t)(s0 + smp) * 64 + 32 + i];
        sJ[smp * 32 + i] = g_jl[(size_t)(s0 + smp) * 64 + i];
    }
    __syncthreads();

    // ---- per-sample GE solve: warps 0 (s0) and 8 (s1) ----
    if (wid == 0 || wid == 8) {
        int ss = wid >> 3;
        float* Hm = sH + ss * 2080;
        float* M  = sM + ss * 1056;
        float rhs = sJ[ss * 32 + lane];
        for (int c = 0; c < 32; c++) rhs -= Hm[lane * 65 + c] * sQ[ss * 32 + c];
        for (int j = 0; j < 32; j++) M[lane * 33 + j] = Hm[lane * 65 + 32 + j];
        M[lane * 33 + 32] = rhs;
        __syncwarp();
        for (int k = 0; k < 32; k++) {
            float v = (lane >= k) ? fabsf(M[lane * 33 + k]) : -1.0f;
            int p = lane;
#pragma unroll
            for (int off = 16; off; off >>= 1) {
                float v2 = __shfl_xor_sync(0xffffffffu, v, off);
                int   p2 = __shfl_xor_sync(0xffffffffu, p, off);
                if (v2 > v || (v2 == v && p2 < p)) { v = v2; p = p2; }
            }
            if (p != k) {
                float a = M[k * 33 + lane], b = M[p * 33 + lane];
                M[k * 33 + lane] = b; M[p * 33 + lane] = a;
                if (lane == 0) {
                    float a2 = M[k * 33 + 32], b2 = M[p * 33 + 32];
                    M[k * 33 + 32] = b2; M[p * 33 + 32] = a2;
                }
            }
            __syncwarp();
            if (lane > k) {
                float f = M[lane * 33 + k] / M[k * 33 + k];
                for (int c = k; c <= 32; c++) M[lane * 33 + c] -= f * M[k * 33 + c];
            }
            __syncwarp();
        }
        float accv = 0.0f;
        for (int k = 31; k >= 0; k--) {
            float xk = 0.0f;
            if (lane == k) xk = (M[k * 33 + 32] - accv) / M[k * 33 + k];
            xk = __shfl_sync(0xffffffffu, xk, k);
            if (lane < k) accv += M[lane * 33 + k] * xk;
            if (lane == k) sX[ss * 32 + k] = xk;
        }
    }
    __syncthreads();
    if (tid < 128) {
        int smp = tid >> 6, i = tid & 63;
        out[(size_t)(s0 + smp) * 64 + i] = (i < 32) ? sQ[smp * 32 + i] : sX[smp * 32 + i - 32];
    }
}

// ---------------- host --------------------------------------------------------
extern "C" void kernel_launch(void* const* d_in, const int* in_sizes, int n_in,
                              void* d_out, int out_size) {
    const float* x   = (const float*)d_in[0];
    const float* mW1 = (const float*)d_in[1];
    const float* mb1 = (const float*)d_in[2];
    const float* mW2 = (const float*)d_in[3];
    const float* mb2 = (const float*)d_in[4];
    const float* mW3 = (const float*)d_in[5];
    const float* qW1 = (const float*)d_in[6];
    const float* qb1 = (const float*)d_in[7];
    const float* qW2 = (const float*)d_in[8];
    const float* qb2 = (const float*)d_in[9];
    const float* qW3 = (const float*)d_in[10];
    float* out = (float*)d_out;

    float *h1, *p1, *p2, *u2, *bv, *wv, *av, *jl, *w1t, *w2t;
    cudaGetSymbolAddress((void**)&h1,  g_h1);
    cudaGetSymbolAddress((void**)&p1,  g_p1);
    cudaGetSymbolAddress((void**)&p2,  g_p2);
    cudaGetSymbolAddress((void**)&u2,  g_u2);
    cudaGetSymbolAddress((void**)&bv,  g_bv);
    cudaGetSymbolAddress((void**)&wv,  g_wv);
    cudaGetSymbolAddress((void**)&av,  g_av);
    cudaGetSymbolAddress((void**)&jl,  g_jl);
    cudaGetSymbolAddress((void**)&w1t, g_W1T);
    cudaGetSymbolAddress((void**)&w2t, g_W2T);

    cudaFuncSetAttribute(k_big, cudaFuncAttributeMaxDynamicSharedMemorySize, SMEM_BYTES);

    k_transpose<<<640, 256>>>(mW1, qW1, mW2, qW2);
    k_prepB<<<512, 256>>>(mW2, qW2);

    dim3 g256(64, 4), g64(64, 1);
    for (int br = 0; br < 2; br++) {
        const float* W1 = br ? qW1 : mW1;
        const float* b1 = br ? qb1 : mb1;
        const float* W2 = br ? qW2 : mW2;
        const float* b2 = br ? qb2 : mb2;
        const float* W3 = br ? qW3 : mW3;
        size_t off = (size_t)br * BROFF;

        k_gemm<<<g256, 256>>>(x, W1, 64, 256, br ? EPI_L1_Q : EPI_L1_SP,
                              b1, nullptr, nullptr, nullptr,
                              h1 + off, p1 + off, p2 + off);
        k_gemm<<<g256, 256>>>(h1 + off, W2, 256, 256, br ? EPI_L2_Q : EPI_L2_SP,
                              b2, W3, nullptr, nullptr,
                              u2 + off, bv + off, nullptr);
        k_gemm<<<g256, 256>>>(u2 + off, w2t + (size_t)br * 65536, 256, 256, EPI_V1,
                              nullptr, nullptr, p1 + off, p2 + off,
                              wv + off, av + off, nullptr);
        k_gemm<<<g64, 256>>>(wv + off, w1t + (size_t)br * 16384, 256, 64,
                             br ? EPI_G_ADD : EPI_G_ST,
                             nullptr, nullptr, nullptr, nullptr,
                             jl, nullptr, nullptr);
    }

    k_big<<<BSZ / 2, 512, SMEM_BYTES>>>(x, out);
}